// round 5
// baseline (speedup 1.0000x reference)
#include <cuda_runtime.h>
#include <cuda_bf16.h>
#include <cstdint>

#define N_NODES 245760
#define N_GRAPHS 8192
#define N_EDGES 1000000
#define NPG 30
#define F_NODE 78
#define HID 64

// ---------------- scratch (static device globals; no allocation) ----------------
__device__ float g_deg[N_NODES];
__device__ float g_dinv[N_NODES];
__device__ float g_A[(size_t)N_GRAPHS * 900];            // 29.5 MB  A[g][dst][src]
__device__ float g_T[(size_t)N_NODES * 256];             // 252 MB   H @ W result
__device__ float g_H[(size_t)N_NODES * 256];             // 252 MB   activations
__device__ float g_pool[(size_t)N_GRAPHS * 256];         // graph means of H3
__device__ float g_drug[(size_t)N_GRAPHS * 64];
__device__ float g_cell1[(size_t)N_GRAPHS * 128];
__device__ float g_cell[(size_t)N_GRAPHS * 64];

// ---------------- edge / degree kernels ----------------
__global__ void init_kernel() {
    int i = blockIdx.x * blockDim.x + threadIdx.x;
    size_t total = (size_t)N_GRAPHS * 900;
    if (i < (int)total) g_A[i] = 0.f;
    if (i < N_NODES) g_deg[i] = 1.0f;   // self-loop
}

__global__ void deg_kernel(const int* __restrict__ ei) {
    int e = blockIdx.x * blockDim.x + threadIdx.x;
    if (e >= N_EDGES) return;
    int dst = ei[N_EDGES + e];
    atomicAdd(&g_deg[dst], 1.0f);
}

__global__ void dinv_kernel() {
    int i = blockIdx.x * blockDim.x + threadIdx.x;
    if (i >= N_NODES) return;
    float dinv = rsqrtf(g_deg[i]);
    g_dinv[i] = dinv;
    int g = i / NPG, l = i % NPG;
    // self-loop diagonal entry (A zeroed before; edge atomics run in a later kernel)
    g_A[(size_t)g * 900 + l * NPG + l] = dinv * dinv;
}

__global__ void buildA_kernel(const int* __restrict__ ei) {
    int e = blockIdx.x * blockDim.x + threadIdx.x;
    if (e >= N_EDGES) return;
    int s = ei[e];
    int d = ei[N_EDGES + e];
    int g = d / NPG;
    int ls = s % NPG, ld = d % NPG;
    float w = g_dinv[s] * g_dinv[d];
    atomicAdd(&g_A[(size_t)g * 900 + ld * NPG + ls], w);
}

// ---------------- generic tiled FP32 GEMM: C = act(A@B [+ bias]) ----------------
// 64x64 block tile, 16 k-tile, 4x4 per thread, 256 threads.
template<bool BIAS, bool RELU>
__global__ void gemm_kernel(const float* __restrict__ A, const float* __restrict__ B,
                            const float* __restrict__ bias, float* __restrict__ C,
                            int M, int N, int K) {
    __shared__ float As[16][64];
    __shared__ float Bs[16][64];
    int tid = threadIdx.x;
    int tx = tid & 15, ty = tid >> 4;
    int rowBase = blockIdx.x * 64;
    int colBase = blockIdx.y * 64;
    float acc[4][4] = {};
    for (int k0 = 0; k0 < K; k0 += 16) {
#pragma unroll
        for (int u = 0; u < 4; u++) {
            int flat = tid + u * 256;
            int m = flat >> 4, kk = flat & 15;
            int gr = rowBase + m, gk = k0 + kk;
            As[kk][m] = (gr < M && gk < K) ? A[(size_t)gr * K + gk] : 0.f;
        }
#pragma unroll
        for (int u = 0; u < 4; u++) {
            int flat = tid + u * 256;
            int kk = flat >> 6, n = flat & 63;
            int gk = k0 + kk, gc = colBase + n;
            Bs[kk][n] = (gk < K && gc < N) ? B[(size_t)gk * N + gc] : 0.f;
        }
        __syncthreads();
#pragma unroll
        for (int kk = 0; kk < 16; kk++) {
            float a[4], b[4];
#pragma unroll
            for (int i = 0; i < 4; i++) a[i] = As[kk][ty * 4 + i];
#pragma unroll
            for (int j = 0; j < 4; j++) b[j] = Bs[kk][tx * 4 + j];
#pragma unroll
            for (int i = 0; i < 4; i++)
#pragma unroll
                for (int j = 0; j < 4; j++) acc[i][j] += a[i] * b[j];
        }
        __syncthreads();
    }
#pragma unroll
    for (int i = 0; i < 4; i++) {
        int r = rowBase + ty * 4 + i;
        if (r >= M) continue;
#pragma unroll
        for (int j = 0; j < 4; j++) {
            int c = colBase + tx * 4 + j;
            if (c >= N) continue;
            float v = acc[i][j];
            if (BIAS) v += bias[c];
            if (RELU) v = fmaxf(v, 0.f);
            C[(size_t)r * N + c] = v;
        }
    }
}

// ---------------- per-graph A-multiply: H = relu(A_g @ T_g + b) ----------------
// block = one graph, blockDim.x == F; optional fused mean-pool (layer 3)
template<int F, bool POOL>
__global__ void amult_kernel(const float* __restrict__ T, const float* __restrict__ bias,
                             float* __restrict__ Hout, float* __restrict__ pool) {
    int g = blockIdx.x;
    __shared__ float sA[900];
    __shared__ float sT[NPG * F];
    const float* Ag = g_A + (size_t)g * 900;
    for (int i = threadIdx.x; i < 900; i += blockDim.x) sA[i] = Ag[i];
    const float* Tg = T + (size_t)g * NPG * F;
    for (int i = threadIdx.x; i < NPG * F; i += blockDim.x) sT[i] = Tg[i];
    __syncthreads();
    int j = threadIdx.x;
    float b = bias[j];
    float colsum = 0.f;
    for (int i = 0; i < NPG; i++) {
        float acc = b;
#pragma unroll
        for (int k = 0; k < NPG; k++) acc += sA[i * NPG + k] * sT[k * F + j];
        acc = fmaxf(acc, 0.f);
        if (POOL) colsum += acc;
        else Hout[((size_t)g * NPG + i) * F + j] = acc;
    }
    if (POOL) pool[(size_t)g * F + j] = colsum * (1.0f / NPG);
}

// ---------------- combiner head: one warp per graph ----------------
__global__ void combiner_kernel(const float* __restrict__ drug, const float* __restrict__ cell,
                                const float* __restrict__ Wm1, const float* __restrict__ bm1,
                                const float* __restrict__ Wm2, const float* __restrict__ bm2,
                                const float* __restrict__ Wo, const float* __restrict__ bo,
                                float* __restrict__ out) {
    int gwarp = (blockIdx.x * blockDim.x + threadIdx.x) >> 5;
    int lane = threadIdx.x & 31;
    int w = threadIdx.x >> 5;
    if (gwarp >= N_GRAPHS) return;
    __shared__ float s_comb[8][128];
    __shared__ float s_z1[8][64];
    __shared__ float s_z2[8][32];
    for (int u = lane; u < 64; u += 32) {
        s_comb[w][u] = drug[(size_t)gwarp * 64 + u];
        s_comb[w][64 + u] = cell[(size_t)gwarp * 64 + u];
    }
    __syncwarp();
    for (int j = lane; j < 64; j += 32) {
        float acc = bm1[j];
        for (int k = 0; k < 128; k++) acc += s_comb[w][k] * Wm1[k * 64 + j];
        s_z1[w][j] = fmaxf(acc, 0.f);
    }
    __syncwarp();
    {
        float acc = bm2[lane];
        for (int k = 0; k < 64; k++) acc += s_z1[w][k] * Wm2[k * 32 + lane];
        s_z2[w][lane] = fmaxf(acc, 0.f);
    }
    __syncwarp();
    float v = s_z2[w][lane] * Wo[lane];
#pragma unroll
    for (int o = 16; o > 0; o >>= 1) v += __shfl_down_sync(0xffffffffu, v, o);
    if (lane == 0) out[gwarp] = v + bo[0];
}

// ---------------- launch ----------------
extern "C" void kernel_launch(void* const* d_in, const int* in_sizes, int n_in,
                              void* d_out, int out_size) {
    const float* x     = (const float*)d_in[0];
    const int*   ei    = (const int*)d_in[1];
    const float* cellf = (const float*)d_in[3];
    const float* W1  = (const float*)d_in[4];
    const float* b1  = (const float*)d_in[5];
    const float* W2  = (const float*)d_in[6];
    const float* b2  = (const float*)d_in[7];
    const float* W3  = (const float*)d_in[8];
    const float* b3  = (const float*)d_in[9];
    const float* Wd  = (const float*)d_in[10];
    const float* bd  = (const float*)d_in[11];
    const float* Wc1 = (const float*)d_in[12];
    const float* bc1 = (const float*)d_in[13];
    const float* Wc2 = (const float*)d_in[14];
    const float* bc2 = (const float*)d_in[15];
    const float* Wm1 = (const float*)d_in[16];
    const float* bm1 = (const float*)d_in[17];
    const float* Wm2 = (const float*)d_in[18];
    const float* bm2 = (const float*)d_in[19];
    const float* Wo  = (const float*)d_in[20];
    const float* bo  = (const float*)d_in[21];
    float* out = (float*)d_out;

    float *dT, *dH, *dPool, *dDrug, *dC1, *dCell;
    cudaGetSymbolAddress((void**)&dT,    g_T);
    cudaGetSymbolAddress((void**)&dH,    g_H);
    cudaGetSymbolAddress((void**)&dPool, g_pool);
    cudaGetSymbolAddress((void**)&dDrug, g_drug);
    cudaGetSymbolAddress((void**)&dC1,   g_cell1);
    cudaGetSymbolAddress((void**)&dCell, g_cell);

    // 1) build normalized adjacency
    init_kernel<<<(N_GRAPHS * 900 + 255) / 256, 256>>>();
    deg_kernel<<<(N_EDGES + 255) / 256, 256>>>(ei);
    dinv_kernel<<<(N_NODES + 255) / 256, 256>>>();
    buildA_kernel<<<(N_EDGES + 255) / 256, 256>>>(ei);

    const int MB = N_NODES / 64;  // 3840

    // 2) GCN layer 1: T = x @ W1 ; H = relu(A@T + b1)
    gemm_kernel<false, false><<<dim3(MB, 1), 256>>>(x, W1, nullptr, dT, N_NODES, 64, F_NODE);
    amult_kernel<64, false><<<N_GRAPHS, 64>>>(dT, b1, dH, nullptr);

    // 3) GCN layer 2
    gemm_kernel<false, false><<<dim3(MB, 2), 256>>>(dH, W2, nullptr, dT, N_NODES, 128, 64);
    amult_kernel<128, false><<<N_GRAPHS, 128>>>(dT, b2, dH, nullptr);

    // 4) GCN layer 3 + fused mean-pool
    gemm_kernel<false, false><<<dim3(MB, 4), 256>>>(dH, W3, nullptr, dT, N_NODES, 256, 128);
    amult_kernel<256, true><<<N_GRAPHS, 256>>>(dT, b3, nullptr, dPool);

    // 5) drug embed: drug = pool @ Wd + bd
    gemm_kernel<true, false><<<dim3(N_GRAPHS / 64, 1), 256>>>(dPool, Wd, bd, dDrug, N_GRAPHS, 64, 256);

    // 6) cell branch
    gemm_kernel<true, true><<<dim3(N_GRAPHS / 64, 2), 256>>>(cellf, Wc1, bc1, dC1, N_GRAPHS, 128, 1000);
    gemm_kernel<true, false><<<dim3(N_GRAPHS / 64, 1), 256>>>(dC1, Wc2, bc2, dCell, N_GRAPHS, 64, 128);

    // 7) combiner head
    combiner_kernel<<<N_GRAPHS / 8, 256>>>(dDrug, dCell, Wm1, bm1, Wm2, bm2, Wo, bo, out);
}

// round 8
// speedup vs baseline: 1.2976x; 1.2976x over previous
#include <cuda_runtime.h>
#include <cuda_bf16.h>
#include <cstdint>

#define N_NODES 245760
#define N_GRAPHS 8192
#define N_EDGES 1000000
#define NPG 30
#define F_NODE 78
#define HID 64

// ---------------- scratch (static device globals; no allocation) ----------------
__device__ float g_deg[N_NODES];
__device__ float g_dinv[N_NODES];
__device__ float g_A[(size_t)N_GRAPHS * 900];            // 29.5 MB  A[g][dst][src]
__device__ float g_T[(size_t)N_NODES * 256];             // H @ W result
__device__ float g_H[(size_t)N_NODES * 256];             // activations
__device__ float g_pool[(size_t)N_GRAPHS * 256];         // graph means of H3
__device__ float g_drug[(size_t)N_GRAPHS * 64];
__device__ float g_cell1[(size_t)N_GRAPHS * 128];
__device__ float g_cell[(size_t)N_GRAPHS * 64];

// ---------------- edge / degree kernels ----------------
__global__ void init_kernel() {
    int i = blockIdx.x * blockDim.x + threadIdx.x;
    size_t total = (size_t)N_GRAPHS * 900;
    if (i < (int)total) g_A[i] = 0.f;
    if (i < N_NODES) g_deg[i] = 1.0f;   // self-loop
}
__global__ void deg_kernel(const int* __restrict__ ei) {
    int e = blockIdx.x * blockDim.x + threadIdx.x;
    if (e >= N_EDGES) return;
    atomicAdd(&g_deg[ei[N_EDGES + e]], 1.0f);
}
__global__ void dinv_kernel() {
    int i = blockIdx.x * blockDim.x + threadIdx.x;
    if (i >= N_NODES) return;
    float dinv = rsqrtf(g_deg[i]);
    g_dinv[i] = dinv;
    int g = i / NPG, l = i % NPG;
    g_A[(size_t)g * 900 + l * NPG + l] = dinv * dinv;
}
__global__ void buildA_kernel(const int* __restrict__ ei) {
    int e = blockIdx.x * blockDim.x + threadIdx.x;
    if (e >= N_EDGES) return;
    int s = ei[e], d = ei[N_EDGES + e];
    int g = d / NPG;
    int ls = s % NPG, ld = d % NPG;
    atomicAdd(&g_A[(size_t)g * 900 + ld * NPG + ls], g_dinv[s] * g_dinv[d]);
}

// ============ mma.sync split-bf16 GEMM: C = act(A[M,K] @ B[K,N] [+bias]) ============
// Block tile 128x64, 8 warps (4M x 2N), warp tile 32x32. K chunks of 32.
// Precision: v = hi(bf16) + lo(bf16); D += hi*hi + hi*lo + lo*hi  (fp32 accum).
// Requires: M % 128 == 0, N % 64 == 0. K arbitrary (zero-filled).
#define ASTRIDE 40   // bf16 elements per smem row (conflict-free fragment loads)

__device__ __forceinline__ void bmma(float* d, const uint32_t* a, const uint32_t* b) {
    asm volatile(
        "mma.sync.aligned.m16n8k16.row.col.f32.bf16.bf16.f32 "
        "{%0,%1,%2,%3},{%4,%5,%6,%7},{%8,%9},{%0,%1,%2,%3};\n"
        : "+f"(d[0]), "+f"(d[1]), "+f"(d[2]), "+f"(d[3])
        : "r"(a[0]), "r"(a[1]), "r"(a[2]), "r"(a[3]), "r"(b[0]), "r"(b[1]));
}

template<bool BIAS, bool RELU>
__global__ void __launch_bounds__(256) mma_gemm(const float* __restrict__ A,
                                                const float* __restrict__ B,
                                                const float* __restrict__ bias,
                                                float* __restrict__ C,
                                                int M, int N, int K) {
    __shared__ __nv_bfloat16 Ahi[128 * ASTRIDE];
    __shared__ __nv_bfloat16 Alo[128 * ASTRIDE];
    __shared__ __nv_bfloat16 Bhi[64 * ASTRIDE];
    __shared__ __nv_bfloat16 Blo[64 * ASTRIDE];

    int tid = threadIdx.x;
    int wid = tid >> 5, lane = tid & 31;
    int wm = wid >> 1, wn = wid & 1;           // warp row/col in block
    int qr = lane >> 2, qc = lane & 3;         // quad row / col within warp
    int rowBase = blockIdx.x * 128;
    int colBase = blockIdx.y * 64;

    float acc[2][4][4];
#pragma unroll
    for (int mt = 0; mt < 2; mt++)
#pragma unroll
        for (int nt = 0; nt < 4; nt++)
#pragma unroll
            for (int i = 0; i < 4; i++) acc[mt][nt][i] = 0.f;

    int KC = (K + 31) / 32;
    for (int c = 0; c < KC; c++) {
        int k0 = c * 32;
        // A chunk: 128 rows x 32 k, coalesced along k
#pragma unroll
        for (int u = 0; u < 16; u++) {
            int idx = tid + u * 256;
            int r = idx >> 5, kk = idx & 31;
            int gk = k0 + kk;
            float v = (gk < K) ? A[(size_t)(rowBase + r) * K + gk] : 0.f;
            __nv_bfloat16 h = __float2bfloat16(v);
            __nv_bfloat16 l = __float2bfloat16(v - __bfloat162float(h));
            Ahi[r * ASTRIDE + kk] = h;
            Alo[r * ASTRIDE + kk] = l;
        }
        // B chunk: stored [n][k]; read W[k][n] row-major, n-fastest for coalescing
#pragma unroll
        for (int u = 0; u < 8; u++) {
            int idx = tid + u * 256;
            int n = idx & 63, kk = idx >> 6;
            int gk = k0 + kk;
            float v = (gk < K) ? B[(size_t)gk * N + colBase + n] : 0.f;
            __nv_bfloat16 h = __float2bfloat16(v);
            __nv_bfloat16 l = __float2bfloat16(v - __bfloat162float(h));
            Bhi[n * ASTRIDE + kk] = h;
            Blo[n * ASTRIDE + kk] = l;
        }
        __syncthreads();

#pragma unroll
        for (int ks = 0; ks < 2; ks++) {
            uint32_t ah[2][4], al[2][4], bh[4][2], bl[4][2];
#pragma unroll
            for (int mt = 0; mt < 2; mt++) {
                int aoff = (wm * 32 + mt * 16 + qr) * ASTRIDE + qc * 2 + ks * 16;
                ah[mt][0] = *(const uint32_t*)&Ahi[aoff];
                ah[mt][1] = *(const uint32_t*)&Ahi[aoff + 8 * ASTRIDE];
                ah[mt][2] = *(const uint32_t*)&Ahi[aoff + 8];
                ah[mt][3] = *(const uint32_t*)&Ahi[aoff + 8 * ASTRIDE + 8];
                al[mt][0] = *(const uint32_t*)&Alo[aoff];
                al[mt][1] = *(const uint32_t*)&Alo[aoff + 8 * ASTRIDE];
                al[mt][2] = *(const uint32_t*)&Alo[aoff + 8];
                al[mt][3] = *(const uint32_t*)&Alo[aoff + 8 * ASTRIDE + 8];
            }
#pragma unroll
            for (int nt = 0; nt < 4; nt++) {
                int boff = (wn * 32 + nt * 8 + qr) * ASTRIDE + qc * 2 + ks * 16;
                bh[nt][0] = *(const uint32_t*)&Bhi[boff];
                bh[nt][1] = *(const uint32_t*)&Bhi[boff + 8];
                bl[nt][0] = *(const uint32_t*)&Blo[boff];
                bl[nt][1] = *(const uint32_t*)&Blo[boff + 8];
            }
#pragma unroll
            for (int mt = 0; mt < 2; mt++)
#pragma unroll
                for (int nt = 0; nt < 4; nt++) {
                    bmma(acc[mt][nt], ah[mt], bh[nt]);
                    bmma(acc[mt][nt], ah[mt], bl[nt]);
                    bmma(acc[mt][nt], al[mt], bh[nt]);
                }
        }
        __syncthreads();
    }

    // epilogue
#pragma unroll
    for (int mt = 0; mt < 2; mt++) {
#pragma unroll
        for (int nt = 0; nt < 4; nt++) {
            int row = rowBase + wm * 32 + mt * 16 + qr;
            int col = colBase + wn * 32 + nt * 8 + qc * 2;
            float v0 = acc[mt][nt][0], v1 = acc[mt][nt][1];
            float v2 = acc[mt][nt][2], v3 = acc[mt][nt][3];
            if (BIAS) {
                float bb0 = bias[col], bb1 = bias[col + 1];
                v0 += bb0; v1 += bb1; v2 += bb0; v3 += bb1;
            }
            if (RELU) {
                v0 = fmaxf(v0, 0.f); v1 = fmaxf(v1, 0.f);
                v2 = fmaxf(v2, 0.f); v3 = fmaxf(v3, 0.f);
            }
            *(float2*)&C[(size_t)row * N + col] = make_float2(v0, v1);
            *(float2*)&C[(size_t)(row + 8) * N + col] = make_float2(v2, v3);
        }
    }
}

// ---------------- fp32 tiled GEMM (small layers) ----------------
template<bool BIAS, bool RELU>
__global__ void gemm_kernel(const float* __restrict__ A, const float* __restrict__ B,
                            const float* __restrict__ bias, float* __restrict__ C,
                            int M, int N, int K) {
    __shared__ float As[16][64];
    __shared__ float Bs[16][64];
    int tid = threadIdx.x;
    int tx = tid & 15, ty = tid >> 4;
    int rowBase = blockIdx.x * 64;
    int colBase = blockIdx.y * 64;
    float acc[4][4] = {};
    for (int k0 = 0; k0 < K; k0 += 16) {
#pragma unroll
        for (int u = 0; u < 4; u++) {
            int flat = tid + u * 256;
            int m = flat >> 4, kk = flat & 15;
            int gr = rowBase + m, gk = k0 + kk;
            As[kk][m] = (gr < M && gk < K) ? A[(size_t)gr * K + gk] : 0.f;
        }
#pragma unroll
        for (int u = 0; u < 4; u++) {
            int flat = tid + u * 256;
            int kk = flat >> 6, n = flat & 63;
            int gk = k0 + kk, gc = colBase + n;
            Bs[kk][n] = (gk < K && gc < N) ? B[(size_t)gk * N + gc] : 0.f;
        }
        __syncthreads();
#pragma unroll
        for (int kk = 0; kk < 16; kk++) {
            float a[4], b[4];
#pragma unroll
            for (int i = 0; i < 4; i++) a[i] = As[kk][ty * 4 + i];
#pragma unroll
            for (int j = 0; j < 4; j++) b[j] = Bs[kk][tx * 4 + j];
#pragma unroll
            for (int i = 0; i < 4; i++)
#pragma unroll
                for (int j = 0; j < 4; j++) acc[i][j] += a[i] * b[j];
        }
        __syncthreads();
    }
#pragma unroll
    for (int i = 0; i < 4; i++) {
        int r = rowBase + ty * 4 + i;
        if (r >= M) continue;
#pragma unroll
        for (int j = 0; j < 4; j++) {
            int c = colBase + tx * 4 + j;
            if (c >= N) continue;
            float v = acc[i][j];
            if (BIAS) v += bias[c];
            if (RELU) v = fmaxf(v, 0.f);
            C[(size_t)r * N + c] = v;
        }
    }
}

// ---------------- per-graph A-multiply: H = relu(A_g @ T_g + b) ----------------
template<int F, bool POOL>
__global__ void amult_kernel(const float* __restrict__ T, const float* __restrict__ bias,
                             float* __restrict__ Hout, float* __restrict__ pool) {
    int g = blockIdx.x;
    __shared__ float sA[900];
    __shared__ float sT[NPG * F];
    const float* Ag = g_A + (size_t)g * 900;
    for (int i = threadIdx.x; i < 900; i += blockDim.x) sA[i] = Ag[i];
    const float* Tg = T + (size_t)g * NPG * F;
    for (int i = threadIdx.x; i < NPG * F; i += blockDim.x) sT[i] = Tg[i];
    __syncthreads();
    int j = threadIdx.x;
    float b = bias[j];
    float colsum = 0.f;
    for (int i = 0; i < NPG; i++) {
        float acc = b;
#pragma unroll
        for (int k = 0; k < NPG; k++) acc += sA[i * NPG + k] * sT[k * F + j];
        acc = fmaxf(acc, 0.f);
        if (POOL) colsum += acc;
        else Hout[((size_t)g * NPG + i) * F + j] = acc;
    }
    if (POOL) pool[(size_t)g * F + j] = colsum * (1.0f / NPG);
}

// ---------------- combiner head: one warp per graph ----------------
__global__ void combiner_kernel(const float* __restrict__ drug, const float* __restrict__ cell,
                                const float* __restrict__ Wm1, const float* __restrict__ bm1,
                                const float* __restrict__ Wm2, const float* __restrict__ bm2,
                                const float* __restrict__ Wo, const float* __restrict__ bo,
                                float* __restrict__ out) {
    int gwarp = (blockIdx.x * blockDim.x + threadIdx.x) >> 5;
    int lane = threadIdx.x & 31;
    int w = threadIdx.x >> 5;
    if (gwarp >= N_GRAPHS) return;
    __shared__ float s_comb[8][128];
    __shared__ float s_z1[8][64];
    __shared__ float s_z2[8][32];
    for (int u = lane; u < 64; u += 32) {
        s_comb[w][u] = drug[(size_t)gwarp * 64 + u];
        s_comb[w][64 + u] = cell[(size_t)gwarp * 64 + u];
    }
    __syncwarp();
    for (int j = lane; j < 64; j += 32) {
        float acc = bm1[j];
        for (int k = 0; k < 128; k++) acc += s_comb[w][k] * Wm1[k * 64 + j];
        s_z1[w][j] = fmaxf(acc, 0.f);
    }
    __syncwarp();
    {
        float acc = bm2[lane];
        for (int k = 0; k < 64; k++) acc += s_z1[w][k] * Wm2[k * 32 + lane];
        s_z2[w][lane] = fmaxf(acc, 0.f);
    }
    __syncwarp();
    float v = s_z2[w][lane] * Wo[lane];
#pragma unroll
    for (int o = 16; o > 0; o >>= 1) v += __shfl_down_sync(0xffffffffu, v, o);
    if (lane == 0) out[gwarp] = v + bo[0];
}

// ---------------- launch ----------------
extern "C" void kernel_launch(void* const* d_in, const int* in_sizes, int n_in,
                              void* d_out, int out_size) {
    const float* x     = (const float*)d_in[0];
    const int*   ei    = (const int*)d_in[1];
    const float* cellf = (const float*)d_in[3];
    const float* W1  = (const float*)d_in[4];
    const float* b1  = (const float*)d_in[5];
    const float* W2  = (const float*)d_in[6];
    const float* b2  = (const float*)d_in[7];
    const float* W3  = (const float*)d_in[8];
    const float* b3  = (const float*)d_in[9];
    const float* Wd  = (const float*)d_in[10];
    const float* bd  = (const float*)d_in[11];
    const float* Wc1 = (const float*)d_in[12];
    const float* bc1 = (const float*)d_in[13];
    const float* Wc2 = (const float*)d_in[14];
    const float* bc2 = (const float*)d_in[15];
    const float* Wm1 = (const float*)d_in[16];
    const float* bm1 = (const float*)d_in[17];
    const float* Wm2 = (const float*)d_in[18];
    const float* bm2 = (const float*)d_in[19];
    const float* Wo  = (const float*)d_in[20];
    const float* bo  = (const float*)d_in[21];
    float* out = (float*)d_out;

    float *dT, *dH, *dPool, *dDrug, *dC1, *dCell;
    cudaGetSymbolAddress((void**)&dT,    g_T);
    cudaGetSymbolAddress((void**)&dH,    g_H);
    cudaGetSymbolAddress((void**)&dPool, g_pool);
    cudaGetSymbolAddress((void**)&dDrug, g_drug);
    cudaGetSymbolAddress((void**)&dC1,   g_cell1);
    cudaGetSymbolAddress((void**)&dCell, g_cell);

    // 1) build normalized adjacency
    init_kernel<<<(N_GRAPHS * 900 + 255) / 256, 256>>>();
    deg_kernel<<<(N_EDGES + 255) / 256, 256>>>(ei);
    dinv_kernel<<<(N_NODES + 255) / 256, 256>>>();
    buildA_kernel<<<(N_EDGES + 255) / 256, 256>>>(ei);

    const int MT = N_NODES / 128;  // 1920

    // 2) GCN layer 1: T = x @ W1 ; H = relu(A@T + b1)
    mma_gemm<false, false><<<dim3(MT, 1), 256>>>(x, W1, nullptr, dT, N_NODES, 64, F_NODE);
    amult_kernel<64, false><<<N_GRAPHS, 64>>>(dT, b1, dH, nullptr);

    // 3) GCN layer 2
    mma_gemm<false, false><<<dim3(MT, 2), 256>>>(dH, W2, nullptr, dT, N_NODES, 128, 64);
    amult_kernel<128, false><<<N_GRAPHS, 128>>>(dT, b2, dH, nullptr);

    // 4) GCN layer 3 + fused mean-pool
    mma_gemm<false, false><<<dim3(MT, 4), 256>>>(dH, W3, nullptr, dT, N_NODES, 256, 128);
    amult_kernel<256, true><<<N_GRAPHS, 256>>>(dT, b3, nullptr, dPool);

    // 5) drug embed: drug = pool @ Wd + bd (fp32, tiny)
    gemm_kernel<true, false><<<dim3(N_GRAPHS / 64, 1), 256>>>(dPool, Wd, bd, dDrug, N_GRAPHS, 64, 256);

    // 6) cell branch: fc1 on tensor cores (K=1000), fc2 fp32
    mma_gemm<true, true><<<dim3(N_GRAPHS / 128, 2), 256>>>(cellf, Wc1, bc1, dC1, N_GRAPHS, 128, 1000);
    gemm_kernel<true, false><<<dim3(N_GRAPHS / 64, 1), 256>>>(dC1, Wc2, bc2, dCell, N_GRAPHS, 64, 128);

    // 7) combiner head
    combiner_kernel<<<N_GRAPHS / 8, 256>>>(dDrug, dCell, Wm1, bm1, Wm2, bm2, Wo, bo, out);
}

// round 9
// speedup vs baseline: 1.6240x; 1.2516x over previous
#include <cuda_runtime.h>
#include <cuda_bf16.h>
#include <cstdint>

#define N_NODES 245760
#define N_GRAPHS 8192
#define N_EDGES 1000000
#define NPG 30
#define F_NODE 78
#define HID 64

// ---------------- scratch (static device globals; no allocation) ----------------
__device__ float g_deg[N_NODES];
__device__ float g_dinv[N_NODES];
__device__ float g_A[(size_t)N_GRAPHS * 900];            // 29.5 MB  A[g][dst][src]
__device__ float g_H1[(size_t)N_GRAPHS * 32 * 64];       // padded activations L1 out
__device__ float g_H2[(size_t)N_GRAPHS * 32 * 128];      // padded activations L2 out
__device__ float g_pool[(size_t)N_GRAPHS * 256];         // graph means of H3
__device__ float g_drug[(size_t)N_GRAPHS * 64];
__device__ float g_cell1[(size_t)N_GRAPHS * 128];
__device__ float g_cell[(size_t)N_GRAPHS * 64];

// ---------------- edge / degree kernels ----------------
__global__ void init_kernel() {
    int i = blockIdx.x * blockDim.x + threadIdx.x;
    size_t total = (size_t)N_GRAPHS * 900;
    if (i < (int)total) g_A[i] = 0.f;
    if (i < N_NODES) g_deg[i] = 1.0f;   // self-loop
}
__global__ void deg_kernel(const int* __restrict__ ei) {
    int e = blockIdx.x * blockDim.x + threadIdx.x;
    if (e >= N_EDGES) return;
    atomicAdd(&g_deg[ei[N_EDGES + e]], 1.0f);
}
__global__ void dinv_kernel() {
    int i = blockIdx.x * blockDim.x + threadIdx.x;
    if (i >= N_NODES) return;
    float dinv = rsqrtf(g_deg[i]);
    g_dinv[i] = dinv;
    int g = i / NPG, l = i % NPG;
    g_A[(size_t)g * 900 + l * NPG + l] = dinv * dinv;
}
__global__ void buildA_kernel(const int* __restrict__ ei) {
    int e = blockIdx.x * blockDim.x + threadIdx.x;
    if (e >= N_EDGES) return;
    int s = ei[e], d = ei[N_EDGES + e];
    int g = d / NPG;
    int ls = s % NPG, ld = d % NPG;
    atomicAdd(&g_A[(size_t)g * 900 + ld * NPG + ls], g_dinv[s] * g_dinv[d]);
}

// ---------------- mma helpers ----------------
#define ASTRIDE 40    // bank-conflict-free A/GA smem stride (bf16 elems)
#define SSTRIDE 136   // bank-conflict-free S^T smem stride (bf16 elems)

__device__ __forceinline__ void bmma(float* d, const uint32_t* a, const uint32_t* b) {
    asm volatile(
        "mma.sync.aligned.m16n8k16.row.col.f32.bf16.bf16.f32 "
        "{%0,%1,%2,%3},{%4,%5,%6,%7},{%8,%9},{%0,%1,%2,%3};\n"
        : "+f"(d[0]), "+f"(d[1]), "+f"(d[2]), "+f"(d[3])
        : "r"(a[0]), "r"(a[1]), "r"(a[2]), "r"(a[3]), "r"(b[0]), "r"(b[1]));
}
__device__ __forceinline__ void split_bf16(float v, __nv_bfloat16& h, __nv_bfloat16& l) {
    h = __float2bfloat16(v);
    l = __float2bfloat16(v - __bfloat162float(h));
}

// ============ fused GCN layer on padded-32 layout ============
// Block: 256 threads (8 warps), covers 4 graphs (128 padded rows) x 64 feats.
// Phase1: S = Hin @ W (split-bf16 mma).  Phase2: out = relu(A_g @ S + b) per graph.
// GATHER: read from unpadded x (30 rows/graph).  POOL: write mean over 30 rows only.
template<bool GATHER, bool POOL>
__global__ void __launch_bounds__(256) gcn_layer(const float* __restrict__ Hin,
                                                 const float* __restrict__ W,
                                                 const float* __restrict__ bias,
                                                 float* __restrict__ Hout,
                                                 float* __restrict__ pool,
                                                 int K, int N) {
    extern __shared__ char sm[];
    __nv_bfloat16* AH = (__nv_bfloat16*)(sm);              // 128*40*2 = 10240
    __nv_bfloat16* AL = (__nv_bfloat16*)(sm + 10240);
    __nv_bfloat16* BH = (__nv_bfloat16*)(sm + 20480);      // 64*40*2 = 5120
    __nv_bfloat16* BL = (__nv_bfloat16*)(sm + 25600);
    // phase-2 union (reused after phase-1 reads complete)
    __nv_bfloat16* SH = (__nv_bfloat16*)(sm);              // 64*136*2 = 17408
    __nv_bfloat16* SL = (__nv_bfloat16*)(sm + 17408);
    __nv_bfloat16* GH = (__nv_bfloat16*)(sm + 34816);      // 4*32*40*2 = 10240
    __nv_bfloat16* GL = (__nv_bfloat16*)(sm + 45056);

    int tid = threadIdx.x;
    int wid = tid >> 5, lane = tid & 31;
    int wm = wid >> 1, wn = wid & 1;           // wm = graph-in-block / m-quarter
    int qr = lane >> 2, qc = lane & 3;
    int g0 = blockIdx.x * 4;                   // first graph of block
    int rowBase = blockIdx.x * 128;            // padded row base
    int colBase = blockIdx.y * 64;

    float acc[2][4][4];
#pragma unroll
    for (int mt = 0; mt < 2; mt++)
#pragma unroll
        for (int nt = 0; nt < 4; nt++)
#pragma unroll
            for (int i = 0; i < 4; i++) acc[mt][nt][i] = 0.f;

    // ---------- phase 1: S = Hin @ W ----------
    int KC = (K + 31) / 32;
    for (int c = 0; c < KC; c++) {
        int k0 = c * 32;
#pragma unroll
        for (int u = 0; u < 16; u++) {
            int idx = tid + u * 256;
            int r = idx >> 5, kk = idx & 31;
            int gk = k0 + kk;
            float v;
            if (GATHER) {
                int pr = rowBase + r;
                int gg = pr >> 5, lr = pr & 31;
                v = (lr < NPG && gk < K) ? Hin[(size_t)(gg * NPG + lr) * K + gk] : 0.f;
            } else {
                v = (gk < K) ? Hin[(size_t)(rowBase + r) * K + gk] : 0.f;
            }
            __nv_bfloat16 h, l; split_bf16(v, h, l);
            AH[r * ASTRIDE + kk] = h;
            AL[r * ASTRIDE + kk] = l;
        }
#pragma unroll
        for (int u = 0; u < 8; u++) {
            int idx = tid + u * 256;
            int n = idx & 63, kk = idx >> 6;
            int gk = k0 + kk;
            float v = (gk < K) ? W[(size_t)gk * N + colBase + n] : 0.f;
            __nv_bfloat16 h, l; split_bf16(v, h, l);
            BH[n * ASTRIDE + kk] = h;
            BL[n * ASTRIDE + kk] = l;
        }
        __syncthreads();
#pragma unroll
        for (int ks = 0; ks < 2; ks++) {
            uint32_t ah[2][4], al[2][4], bh[4][2], bl[4][2];
#pragma unroll
            for (int mt = 0; mt < 2; mt++) {
                int aoff = (wm * 32 + mt * 16 + qr) * ASTRIDE + qc * 2 + ks * 16;
                ah[mt][0] = *(const uint32_t*)&AH[aoff];
                ah[mt][1] = *(const uint32_t*)&AH[aoff + 8 * ASTRIDE];
                ah[mt][2] = *(const uint32_t*)&AH[aoff + 8];
                ah[mt][3] = *(const uint32_t*)&AH[aoff + 8 * ASTRIDE + 8];
                al[mt][0] = *(const uint32_t*)&AL[aoff];
                al[mt][1] = *(const uint32_t*)&AL[aoff + 8 * ASTRIDE];
                al[mt][2] = *(const uint32_t*)&AL[aoff + 8];
                al[mt][3] = *(const uint32_t*)&AL[aoff + 8 * ASTRIDE + 8];
            }
#pragma unroll
            for (int nt = 0; nt < 4; nt++) {
                int boff = (wn * 32 + nt * 8 + qr) * ASTRIDE + qc * 2 + ks * 16;
                bh[nt][0] = *(const uint32_t*)&BH[boff];
                bh[nt][1] = *(const uint32_t*)&BH[boff + 8];
                bl[nt][0] = *(const uint32_t*)&BL[boff];
                bl[nt][1] = *(const uint32_t*)&BL[boff + 8];
            }
#pragma unroll
            for (int mt = 0; mt < 2; mt++)
#pragma unroll
                for (int nt = 0; nt < 4; nt++) {
                    bmma(acc[mt][nt], ah[mt], bh[nt]);
                    bmma(acc[mt][nt], ah[mt], bl[nt]);
                    bmma(acc[mt][nt], al[mt], bh[nt]);
                }
        }
        __syncthreads();
    }

    // ---------- phase 2 setup: S^T into smem + A graphs ----------
    // store S transposed: SH[feat][src]  (feat 0..63 local, src 0..127 padded)
#pragma unroll
    for (int mt = 0; mt < 2; mt++)
#pragma unroll
        for (int nt = 0; nt < 4; nt++) {
            int src0 = wm * 32 + mt * 16 + qr;
            int f0 = wn * 32 + nt * 8 + qc * 2;
            __nv_bfloat16 h, l;
            split_bf16(acc[mt][nt][0], h, l); SH[f0 * SSTRIDE + src0] = h; SL[f0 * SSTRIDE + src0] = l;
            split_bf16(acc[mt][nt][1], h, l); SH[(f0 + 1) * SSTRIDE + src0] = h; SL[(f0 + 1) * SSTRIDE + src0] = l;
            split_bf16(acc[mt][nt][2], h, l); SH[f0 * SSTRIDE + src0 + 8] = h; SL[f0 * SSTRIDE + src0 + 8] = l;
            split_bf16(acc[mt][nt][3], h, l); SH[(f0 + 1) * SSTRIDE + src0 + 8] = h; SL[(f0 + 1) * SSTRIDE + src0 + 8] = l;
        }
    // convert 4 graphs' A (30x30 -> padded 32x32, split bf16)
#pragma unroll
    for (int u = 0; u < 16; u++) {
        int i = tid + u * 256;
        int g = i >> 10, rem = i & 1023;
        int dr = rem >> 5, sc = rem & 31;
        float v = (dr < NPG && sc < NPG) ? g_A[(size_t)(g0 + g) * 900 + dr * NPG + sc] : 0.f;
        __nv_bfloat16 h, l; split_bf16(v, h, l);
        GH[g * 1280 + dr * ASTRIDE + sc] = h;
        GL[g * 1280 + dr * ASTRIDE + sc] = l;
    }
    __syncthreads();

    // ---------- phase 2: out = A_g @ S  (warp wm owns graph g0+wm, local src base wm*32) ----------
#pragma unroll
    for (int mt = 0; mt < 2; mt++)
#pragma unroll
        for (int nt = 0; nt < 4; nt++)
#pragma unroll
            for (int i = 0; i < 4; i++) acc[mt][nt][i] = 0.f;

#pragma unroll
    for (int ks = 0; ks < 2; ks++) {
        uint32_t ah[2][4], al[2][4], bh[4][2], bl[4][2];
#pragma unroll
        for (int mt = 0; mt < 2; mt++) {
            int aoff = wm * 1280 + (mt * 16 + qr) * ASTRIDE + qc * 2 + ks * 16;
            ah[mt][0] = *(const uint32_t*)&GH[aoff];
            ah[mt][1] = *(const uint32_t*)&GH[aoff + 8 * ASTRIDE];
            ah[mt][2] = *(const uint32_t*)&GH[aoff + 8];
            ah[mt][3] = *(const uint32_t*)&GH[aoff + 8 * ASTRIDE + 8];
            al[mt][0] = *(const uint32_t*)&GL[aoff];
            al[mt][1] = *(const uint32_t*)&GL[aoff + 8 * ASTRIDE];
            al[mt][2] = *(const uint32_t*)&GL[aoff + 8];
            al[mt][3] = *(const uint32_t*)&GL[aoff + 8 * ASTRIDE + 8];
        }
#pragma unroll
        for (int nt = 0; nt < 4; nt++) {
            // B[k=src within graph][n=feat]: src global = wm*32 + k
            int boff = (wn * 32 + nt * 8 + qr) * SSTRIDE + wm * 32 + qc * 2 + ks * 16;
            bh[nt][0] = *(const uint32_t*)&SH[boff];
            bh[nt][1] = *(const uint32_t*)&SH[boff + 8];
            bl[nt][0] = *(const uint32_t*)&SL[boff];
            bl[nt][1] = *(const uint32_t*)&SL[boff + 8];
        }
#pragma unroll
        for (int mt = 0; mt < 2; mt++)
#pragma unroll
            for (int nt = 0; nt < 4; nt++) {
                bmma(acc[mt][nt], ah[mt], bh[nt]);
                bmma(acc[mt][nt], ah[mt], bl[nt]);
                bmma(acc[mt][nt], al[mt], bh[nt]);
            }
    }

    // ---------- epilogue: bias + relu, write padded H or pooled mean ----------
    int g = g0 + wm;
    float pp[4][2];
#pragma unroll
    for (int nt = 0; nt < 4; nt++) { pp[nt][0] = 0.f; pp[nt][1] = 0.f; }

#pragma unroll
    for (int mt = 0; mt < 2; mt++)
#pragma unroll
        for (int nt = 0; nt < 4; nt++) {
            int dst0 = mt * 16 + qr;           // < 24
            int dst1 = dst0 + 8;               // < 32
            int f = colBase + wn * 32 + nt * 8 + qc * 2;
            float bb0 = bias[f], bb1 = bias[f + 1];
            float v0 = fmaxf(acc[mt][nt][0] + bb0, 0.f);
            float v1 = fmaxf(acc[mt][nt][1] + bb1, 0.f);
            float v2 = fmaxf(acc[mt][nt][2] + bb0, 0.f);
            float v3 = fmaxf(acc[mt][nt][3] + bb1, 0.f);
            if (POOL) {
                pp[nt][0] += v0; pp[nt][1] += v1;
                if (dst1 < NPG) { pp[nt][0] += v2; pp[nt][1] += v3; }
            } else {
                *(float2*)&Hout[((size_t)g * 32 + dst0) * N + f] = make_float2(v0, v1);
                *(float2*)&Hout[((size_t)g * 32 + dst1) * N + f] = make_float2(v2, v3);
            }
        }
    if (POOL) {
#pragma unroll
        for (int nt = 0; nt < 4; nt++) {
#pragma unroll
            for (int o = 4; o < 32; o <<= 1) {
                pp[nt][0] += __shfl_xor_sync(0xffffffffu, pp[nt][0], o);
                pp[nt][1] += __shfl_xor_sync(0xffffffffu, pp[nt][1], o);
            }
            if (qr == 0) {
                int f = colBase + wn * 32 + nt * 8 + qc * 2;
                pool[(size_t)g * N + f]     = pp[nt][0] * (1.0f / NPG);
                pool[(size_t)g * N + f + 1] = pp[nt][1] * (1.0f / NPG);
            }
        }
    }
}

// ============ generic mma split-bf16 GEMM (cell_fc1) ============
template<bool BIAS, bool RELU>
__global__ void __launch_bounds__(256) mma_gemm(const float* __restrict__ A,
                                                const float* __restrict__ B,
                                                const float* __restrict__ bias,
                                                float* __restrict__ C,
                                                int M, int N, int K) {
    __shared__ __nv_bfloat16 Ahi[128 * ASTRIDE];
    __shared__ __nv_bfloat16 Alo[128 * ASTRIDE];
    __shared__ __nv_bfloat16 Bhi[64 * ASTRIDE];
    __shared__ __nv_bfloat16 Blo[64 * ASTRIDE];
    int tid = threadIdx.x;
    int wid = tid >> 5, lane = tid & 31;
    int wm = wid >> 1, wn = wid & 1;
    int qr = lane >> 2, qc = lane & 3;
    int rowBase = blockIdx.x * 128;
    int colBase = blockIdx.y * 64;

    float acc[2][4][4];
#pragma unroll
    for (int mt = 0; mt < 2; mt++)
#pragma unroll
        for (int nt = 0; nt < 4; nt++)
#pragma unroll
            for (int i = 0; i < 4; i++) acc[mt][nt][i] = 0.f;

    int KC = (K + 31) / 32;
    for (int c = 0; c < KC; c++) {
        int k0 = c * 32;
#pragma unroll
        for (int u = 0; u < 16; u++) {
            int idx = tid + u * 256;
            int r = idx >> 5, kk = idx & 31;
            int gk = k0 + kk;
            float v = (gk < K) ? A[(size_t)(rowBase + r) * K + gk] : 0.f;
            __nv_bfloat16 h, l; split_bf16(v, h, l);
            Ahi[r * ASTRIDE + kk] = h;
            Alo[r * ASTRIDE + kk] = l;
        }
#pragma unroll
        for (int u = 0; u < 8; u++) {
            int idx = tid + u * 256;
            int n = idx & 63, kk = idx >> 6;
            int gk = k0 + kk;
            float v = (gk < K) ? B[(size_t)gk * N + colBase + n] : 0.f;
            __nv_bfloat16 h, l; split_bf16(v, h, l);
            Bhi[n * ASTRIDE + kk] = h;
            Blo[n * ASTRIDE + kk] = l;
        }
        __syncthreads();
#pragma unroll
        for (int ks = 0; ks < 2; ks++) {
            uint32_t ah[2][4], al[2][4], bh[4][2], bl[4][2];
#pragma unroll
            for (int mt = 0; mt < 2; mt++) {
                int aoff = (wm * 32 + mt * 16 + qr) * ASTRIDE + qc * 2 + ks * 16;
                ah[mt][0] = *(const uint32_t*)&Ahi[aoff];
                ah[mt][1] = *(const uint32_t*)&Ahi[aoff + 8 * ASTRIDE];
                ah[mt][2] = *(const uint32_t*)&Ahi[aoff + 8];
                ah[mt][3] = *(const uint32_t*)&Ahi[aoff + 8 * ASTRIDE + 8];
                al[mt][0] = *(const uint32_t*)&Alo[aoff];
                al[mt][1] = *(const uint32_t*)&Alo[aoff + 8 * ASTRIDE];
                al[mt][2] = *(const uint32_t*)&Alo[aoff + 8];
                al[mt][3] = *(const uint32_t*)&Alo[aoff + 8 * ASTRIDE + 8];
            }
#pragma unroll
            for (int nt = 0; nt < 4; nt++) {
                int boff = (wn * 32 + nt * 8 + qr) * ASTRIDE + qc * 2 + ks * 16;
                bh[nt][0] = *(const uint32_t*)&Bhi[boff];
                bh[nt][1] = *(const uint32_t*)&Bhi[boff + 8];
                bl[nt][0] = *(const uint32_t*)&Blo[boff];
                bl[nt][1] = *(const uint32_t*)&Blo[boff + 8];
            }
#pragma unroll
            for (int mt = 0; mt < 2; mt++)
#pragma unroll
                for (int nt = 0; nt < 4; nt++) {
                    bmma(acc[mt][nt], ah[mt], bh[nt]);
                    bmma(acc[mt][nt], ah[mt], bl[nt]);
                    bmma(acc[mt][nt], al[mt], bh[nt]);
                }
        }
        __syncthreads();
    }
#pragma unroll
    for (int mt = 0; mt < 2; mt++)
#pragma unroll
        for (int nt = 0; nt < 4; nt++) {
            int row = rowBase + wm * 32 + mt * 16 + qr;
            int col = colBase + wn * 32 + nt * 8 + qc * 2;
            float v0 = acc[mt][nt][0], v1 = acc[mt][nt][1];
            float v2 = acc[mt][nt][2], v3 = acc[mt][nt][3];
            if (BIAS) {
                float bb0 = bias[col], bb1 = bias[col + 1];
                v0 += bb0; v1 += bb1; v2 += bb0; v3 += bb1;
            }
            if (RELU) {
                v0 = fmaxf(v0, 0.f); v1 = fmaxf(v1, 0.f);
                v2 = fmaxf(v2, 0.f); v3 = fmaxf(v3, 0.f);
            }
            *(float2*)&C[(size_t)row * N + col] = make_float2(v0, v1);
            *(float2*)&C[(size_t)(row + 8) * N + col] = make_float2(v2, v3);
        }
}

// ---------------- fp32 tiled GEMM (small layers) ----------------
template<bool BIAS, bool RELU>
__global__ void gemm_kernel(const float* __restrict__ A, const float* __restrict__ B,
                            const float* __restrict__ bias, float* __restrict__ C,
                            int M, int N, int K) {
    __shared__ float As[16][64];
    __shared__ float Bs[16][64];
    int tid = threadIdx.x;
    int tx = tid & 15, ty = tid >> 4;
    int rowBase = blockIdx.x * 64;
    int colBase = blockIdx.y * 64;
    float acc[4][4] = {};
    for (int k0 = 0; k0 < K; k0 += 16) {
#pragma unroll
        for (int u = 0; u < 4; u++) {
            int flat = tid + u * 256;
            int m = flat >> 4, kk = flat & 15;
            int gr = rowBase + m, gk = k0 + kk;
            As[kk][m] = (gr < M && gk < K) ? A[(size_t)gr * K + gk] : 0.f;
        }
#pragma unroll
        for (int u = 0; u < 4; u++) {
            int flat = tid + u * 256;
            int kk = flat >> 6, n = flat & 63;
            int gk = k0 + kk, gc = colBase + n;
            Bs[kk][n] = (gk < K && gc < N) ? B[(size_t)gk * N + gc] : 0.f;
        }
        __syncthreads();
#pragma unroll
        for (int kk = 0; kk < 16; kk++) {
            float a[4], b[4];
#pragma unroll
            for (int i = 0; i < 4; i++) a[i] = As[kk][ty * 4 + i];
#pragma unroll
            for (int j = 0; j < 4; j++) b[j] = Bs[kk][tx * 4 + j];
#pragma unroll
            for (int i = 0; i < 4; i++)
#pragma unroll
                for (int j = 0; j < 4; j++) acc[i][j] += a[i] * b[j];
        }
        __syncthreads();
    }
#pragma unroll
    for (int i = 0; i < 4; i++) {
        int r = rowBase + ty * 4 + i;
        if (r >= M) continue;
#pragma unroll
        for (int j = 0; j < 4; j++) {
            int c = colBase + tx * 4 + j;
            if (c >= N) continue;
            float v = acc[i][j];
            if (BIAS) v += bias[c];
            if (RELU) v = fmaxf(v, 0.f);
            C[(size_t)r * N + c] = v;
        }
    }
}

// ---------------- combiner head: one warp per graph ----------------
__global__ void combiner_kernel(const float* __restrict__ drug, const float* __restrict__ cell,
                                const float* __restrict__ Wm1, const float* __restrict__ bm1,
                                const float* __restrict__ Wm2, const float* __restrict__ bm2,
                                const float* __restrict__ Wo, const float* __restrict__ bo,
                                float* __restrict__ out) {
    int gwarp = (blockIdx.x * blockDim.x + threadIdx.x) >> 5;
    int lane = threadIdx.x & 31;
    int w = threadIdx.x >> 5;
    if (gwarp >= N_GRAPHS) return;
    __shared__ float s_comb[8][128];
    __shared__ float s_z1[8][64];
    __shared__ float s_z2[8][32];
    for (int u = lane; u < 64; u += 32) {
        s_comb[w][u] = drug[(size_t)gwarp * 64 + u];
        s_comb[w][64 + u] = cell[(size_t)gwarp * 64 + u];
    }
    __syncwarp();
    for (int j = lane; j < 64; j += 32) {
        float acc = bm1[j];
        for (int k = 0; k < 128; k++) acc += s_comb[w][k] * Wm1[k * 64 + j];
        s_z1[w][j] = fmaxf(acc, 0.f);
    }
    __syncwarp();
    {
        float acc = bm2[lane];
        for (int k = 0; k < 64; k++) acc += s_z1[w][k] * Wm2[k * 32 + lane];
        s_z2[w][lane] = fmaxf(acc, 0.f);
    }
    __syncwarp();
    float v = s_z2[w][lane] * Wo[lane];
#pragma unroll
    for (int o = 16; o > 0; o >>= 1) v += __shfl_down_sync(0xffffffffu, v, o);
    if (lane == 0) out[gwarp] = v + bo[0];
}

// ---------------- launch ----------------
extern "C" void kernel_launch(void* const* d_in, const int* in_sizes, int n_in,
                              void* d_out, int out_size) {
    const float* x     = (const float*)d_in[0];
    const int*   ei    = (const int*)d_in[1];
    const float* cellf = (const float*)d_in[3];
    const float* W1  = (const float*)d_in[4];
    const float* b1  = (const float*)d_in[5];
    const float* W2  = (const float*)d_in[6];
    const float* b2  = (const float*)d_in[7];
    const float* W3  = (const float*)d_in[8];
    const float* b3  = (const float*)d_in[9];
    const float* Wd  = (const float*)d_in[10];
    const float* bd  = (const float*)d_in[11];
    const float* Wc1 = (const float*)d_in[12];
    const float* bc1 = (const float*)d_in[13];
    const float* Wc2 = (const float*)d_in[14];
    const float* bc2 = (const float*)d_in[15];
    const float* Wm1 = (const float*)d_in[16];
    const float* bm1 = (const float*)d_in[17];
    const float* Wm2 = (const float*)d_in[18];
    const float* bm2 = (const float*)d_in[19];
    const float* Wo  = (const float*)d_in[20];
    const float* bo  = (const float*)d_in[21];
    float* out = (float*)d_out;

    float *dH1, *dH2, *dPool, *dDrug, *dC1, *dCell;
    cudaGetSymbolAddress((void**)&dH1,   g_H1);
    cudaGetSymbolAddress((void**)&dH2,   g_H2);
    cudaGetSymbolAddress((void**)&dPool, g_pool);
    cudaGetSymbolAddress((void**)&dDrug, g_drug);
    cudaGetSymbolAddress((void**)&dC1,   g_cell1);
    cudaGetSymbolAddress((void**)&dCell, g_cell);

    const int GCN_SMEM = 55296;
    cudaFuncSetAttribute(gcn_layer<true,  false>, cudaFuncAttributeMaxDynamicSharedMemorySize, GCN_SMEM);
    cudaFuncSetAttribute(gcn_layer<false, false>, cudaFuncAttributeMaxDynamicSharedMemorySize, GCN_SMEM);
    cudaFuncSetAttribute(gcn_layer<false, true>,  cudaFuncAttributeMaxDynamicSharedMemorySize, GCN_SMEM);

    // 1) build normalized adjacency
    init_kernel<<<(N_GRAPHS * 900 + 255) / 256, 256>>>();
    deg_kernel<<<(N_EDGES + 255) / 256, 256>>>(ei);
    dinv_kernel<<<(N_NODES + 255) / 256, 256>>>();
    buildA_kernel<<<(N_EDGES + 255) / 256, 256>>>(ei);

    const int GB = N_GRAPHS / 4;  // 2048 blocks (4 graphs each)

    // 2) three fused GCN layers (padded-32 layout between layers)
    gcn_layer<true,  false><<<dim3(GB, 1), 256, GCN_SMEM>>>(x,   W1, b1, dH1, nullptr, F_NODE, 64);
    gcn_layer<false, false><<<dim3(GB, 2), 256, GCN_SMEM>>>(dH1, W2, b2, dH2, nullptr, 64, 128);
    gcn_layer<false, true ><<<dim3(GB, 4), 256, GCN_SMEM>>>(dH2, W3, b3, nullptr, dPool, 128, 256);

    // 3) drug embed: drug = pool @ Wd + bd (fp32, tiny)
    gemm_kernel<true, false><<<dim3(N_GRAPHS / 64, 1), 256>>>(dPool, Wd, bd, dDrug, N_GRAPHS, 64, 256);

    // 4) cell branch: fc1 on tensor cores (K=1000), fc2 fp32
    mma_gemm<true, true><<<dim3(N_GRAPHS / 128, 2), 256>>>(cellf, Wc1, bc1, dC1, N_GRAPHS, 128, 1000);
    gemm_kernel<true, false><<<dim3(N_GRAPHS / 64, 1), 256>>>(dC1, Wc2, bc2, dCell, N_GRAPHS, 64, 128);

    // 5) combiner head
    combiner_kernel<<<N_GRAPHS / 8, 256>>>(dDrug, dCell, Wm1, bm1, Wm2, bm2, Wo, bo, out);
}

// round 10
// speedup vs baseline: 1.7610x; 1.0843x over previous
#include <cuda_runtime.h>
#include <cuda_bf16.h>
#include <cstdint>

#define N_NODES 245760
#define N_GRAPHS 8192
#define N_EDGES 1000000
#define NPG 30
#define F_NODE 78
#define HID 64

// weight plane offsets (transposed [n][k] layout)
#define WOFF1 0
#define WOFF2 4992        // 78*64
#define WOFF3 13184       // +64*128
#define WOFFC 45952       // +128*256
#define WTOT  173952      // +1000*128

// ---------------- scratch (static device globals; no allocation) ----------------
__device__ float g_deg[N_NODES];
__device__ float g_dinv[N_NODES];
__device__ float g_A[(size_t)N_GRAPHS * 900];            // 29.5 MB  A[g][dst][src]
__device__ __nv_bfloat16 g_xh[(size_t)N_NODES * F_NODE];
__device__ __nv_bfloat16 g_xl[(size_t)N_NODES * F_NODE];
__device__ __nv_bfloat16 g_wh[WTOT];
__device__ __nv_bfloat16 g_wl[WTOT];
__device__ __nv_bfloat16 g_ch[(size_t)N_GRAPHS * 1000];
__device__ __nv_bfloat16 g_cl[(size_t)N_GRAPHS * 1000];
__device__ __nv_bfloat16 g_h1h[(size_t)N_GRAPHS * 32 * 64];
__device__ __nv_bfloat16 g_h1l[(size_t)N_GRAPHS * 32 * 64];
__device__ __nv_bfloat16 g_h2h[(size_t)N_GRAPHS * 32 * 128];
__device__ __nv_bfloat16 g_h2l[(size_t)N_GRAPHS * 32 * 128];
__device__ float g_pool[(size_t)N_GRAPHS * 256];
__device__ float g_drug[(size_t)N_GRAPHS * 64];
__device__ float g_cell1[(size_t)N_GRAPHS * 128];
__device__ float g_cell[(size_t)N_GRAPHS * 64];

__device__ __forceinline__ void split_bf16(float v, __nv_bfloat16& h, __nv_bfloat16& l) {
    h = __float2bfloat16(v);
    l = __float2bfloat16(v - __bfloat162float(h));
}

// ---------------- setup: pre-split inputs / weights ----------------
__global__ void split_pairs_kernel(const float2* __restrict__ in,
                                   __nv_bfloat162* __restrict__ oh,
                                   __nv_bfloat162* __restrict__ ol, int npairs) {
    int i = blockIdx.x * blockDim.x + threadIdx.x;
    if (i >= npairs) return;
    float2 v = in[i];
    __nv_bfloat16 h0, l0, h1, l1;
    split_bf16(v.x, h0, l0);
    split_bf16(v.y, h1, l1);
    __nv_bfloat162 H; H.x = h0; H.y = h1;
    __nv_bfloat162 L; L.x = l0; L.y = l1;
    oh[i] = H; ol[i] = L;
}

__global__ void split_w_kernel(const float* __restrict__ W1, const float* __restrict__ W2,
                               const float* __restrict__ W3, const float* __restrict__ Wc1) {
    int i = blockIdx.x * blockDim.x + threadIdx.x;
    const float* src; int K, N, off, j;
    if (i < WOFF2)      { src = W1;  K = 78;   N = 64;  off = WOFF1; j = i; }
    else if (i < WOFF3) { src = W2;  K = 64;   N = 128; off = WOFF2; j = i - WOFF2; }
    else if (i < WOFFC) { src = W3;  K = 128;  N = 256; off = WOFF3; j = i - WOFF3; }
    else if (i < WTOT)  { src = Wc1; K = 1000; N = 128; off = WOFFC; j = i - WOFFC; }
    else return;
    int n = j / K, k = j % K;
    float v = src[(size_t)k * N + n];
    __nv_bfloat16 h, l; split_bf16(v, h, l);
    g_wh[off + j] = h;
    g_wl[off + j] = l;
}

// ---------------- edge / degree kernels ----------------
__global__ void init_kernel() {
    int i = blockIdx.x * blockDim.x + threadIdx.x;
    size_t total = (size_t)N_GRAPHS * 900;
    if (i < (int)total) g_A[i] = 0.f;
    if (i < N_NODES) g_deg[i] = 1.0f;   // self-loop
}
__global__ void deg_kernel(const int* __restrict__ ei) {
    int e = blockIdx.x * blockDim.x + threadIdx.x;
    if (e >= N_EDGES) return;
    atomicAdd(&g_deg[ei[N_EDGES + e]], 1.0f);
}
__global__ void dinv_kernel() {
    int i = blockIdx.x * blockDim.x + threadIdx.x;
    if (i >= N_NODES) return;
    float dinv = rsqrtf(g_deg[i]);
    g_dinv[i] = dinv;
    int g = i / NPG, l = i % NPG;
    g_A[(size_t)g * 900 + l * NPG + l] = dinv * dinv;
}
__global__ void buildA_kernel(const int* __restrict__ ei) {
    int e = blockIdx.x * blockDim.x + threadIdx.x;
    if (e >= N_EDGES) return;
    int s = ei[e], d = ei[N_EDGES + e];
    int g = d / NPG;
    int ls = s % NPG, ld = d % NPG;
    atomicAdd(&g_A[(size_t)g * 900 + ld * NPG + ls], g_dinv[s] * g_dinv[d]);
}

// ---------------- mma helpers ----------------
#define ASTRIDE 40    // bank-conflict-free A/GA smem stride (bf16 elems)
#define SSTRIDE 136   // bank-conflict-free S^T smem stride (bf16 elems)

__device__ __forceinline__ void bmma(float* d, const uint32_t* a, const uint32_t* b) {
    asm volatile(
        "mma.sync.aligned.m16n8k16.row.col.f32.bf16.bf16.f32 "
        "{%0,%1,%2,%3},{%4,%5,%6,%7},{%8,%9},{%0,%1,%2,%3};\n"
        : "+f"(d[0]), "+f"(d[1]), "+f"(d[2]), "+f"(d[3])
        : "r"(a[0]), "r"(a[1]), "r"(a[2]), "r"(a[3]), "r"(b[0]), "r"(b[1]));
}

// ============ fused GCN layer on padded-32 layout (plane inputs) ============
// Block: 256 threads (8 warps), 4 graphs (128 padded rows) x 64 feats.
// Phase1: S = Hin @ W (pre-split bf16 planes). Phase2: out = relu(A_g @ S + b).
template<bool GATHER, bool POOL>
__global__ void __launch_bounds__(256) gcn_layer(const __nv_bfloat16* __restrict__ Hh,
                                                 const __nv_bfloat16* __restrict__ Hl,
                                                 const __nv_bfloat16* __restrict__ Wth,
                                                 const __nv_bfloat16* __restrict__ Wtl,
                                                 const float* __restrict__ bias,
                                                 __nv_bfloat16* __restrict__ Oh,
                                                 __nv_bfloat16* __restrict__ Ol,
                                                 float* __restrict__ pool,
                                                 int K, int N) {
    extern __shared__ char sm[];
    __nv_bfloat16* AH = (__nv_bfloat16*)(sm);              // 128*40*2 = 10240
    __nv_bfloat16* AL = (__nv_bfloat16*)(sm + 10240);
    __nv_bfloat16* BH = (__nv_bfloat16*)(sm + 20480);      // 64*40*2 = 5120
    __nv_bfloat16* BL = (__nv_bfloat16*)(sm + 25600);
    // phase-2 union (reused after phase-1 reads complete)
    __nv_bfloat16* SH = (__nv_bfloat16*)(sm);              // 64*136*2 = 17408
    __nv_bfloat16* SL = (__nv_bfloat16*)(sm + 17408);
    __nv_bfloat16* GH = (__nv_bfloat16*)(sm + 34816);      // 4*32*40*2 = 10240
    __nv_bfloat16* GL = (__nv_bfloat16*)(sm + 45056);

    int tid = threadIdx.x;
    int wid = tid >> 5, lane = tid & 31;
    int wm = wid >> 1, wn = wid & 1;
    int qr = lane >> 2, qc = lane & 3;
    int g0 = blockIdx.x * 4;
    int rowBase = blockIdx.x * 128;
    int colBase = blockIdx.y * 64;

    float acc[2][4][4];
#pragma unroll
    for (int mt = 0; mt < 2; mt++)
#pragma unroll
        for (int nt = 0; nt < 4; nt++)
#pragma unroll
            for (int i = 0; i < 4; i++) acc[mt][nt][i] = 0.f;

    // ---------- phase 1: S = Hin @ W ----------
    int KC = (K + 31) / 32;
    for (int c = 0; c < KC; c++) {
        int k0 = c * 32;
        // A chunk: 128 rows x 16 uint32 (2 bf16 each)
#pragma unroll
        for (int u = 0; u < 8; u++) {
            int slot = tid + u * 256;
            int r = slot >> 4, p = slot & 15;
            int k = k0 + p * 2;
            uint32_t uh = 0, ul = 0;
            if (GATHER) {
                int pr = rowBase + r, gg = pr >> 5, lr = pr & 31;
                if (lr < NPG && k < K) {
                    size_t off = (size_t)(gg * NPG + lr) * K + k;
                    uh = *(const uint32_t*)&Hh[off];
                    ul = *(const uint32_t*)&Hl[off];
                }
            } else {
                if (k < K) {
                    size_t off = (size_t)(rowBase + r) * K + k;
                    uh = *(const uint32_t*)&Hh[off];
                    ul = *(const uint32_t*)&Hl[off];
                }
            }
            *(uint32_t*)&AH[r * ASTRIDE + p * 2] = uh;
            *(uint32_t*)&AL[r * ASTRIDE + p * 2] = ul;
        }
        // W chunk from transposed planes [n][k]
#pragma unroll
        for (int u = 0; u < 4; u++) {
            int slot = tid + u * 256;
            int n = slot >> 4, p = slot & 15;
            int k = k0 + p * 2;
            uint32_t uh = 0, ul = 0;
            if (k < K) {
                size_t off = (size_t)(colBase + n) * K + k;
                uh = *(const uint32_t*)&Wth[off];
                ul = *(const uint32_t*)&Wtl[off];
            }
            *(uint32_t*)&BH[n * ASTRIDE + p * 2] = uh;
            *(uint32_t*)&BL[n * ASTRIDE + p * 2] = ul;
        }
        __syncthreads();
#pragma unroll
        for (int ks = 0; ks < 2; ks++) {
            uint32_t ah[2][4], al[2][4], bh[4][2], bl[4][2];
#pragma unroll
            for (int mt = 0; mt < 2; mt++) {
                int aoff = (wm * 32 + mt * 16 + qr) * ASTRIDE + qc * 2 + ks * 16;
                ah[mt][0] = *(const uint32_t*)&AH[aoff];
                ah[mt][1] = *(const uint32_t*)&AH[aoff + 8 * ASTRIDE];
                ah[mt][2] = *(const uint32_t*)&AH[aoff + 8];
                ah[mt][3] = *(const uint32_t*)&AH[aoff + 8 * ASTRIDE + 8];
                al[mt][0] = *(const uint32_t*)&AL[aoff];
                al[mt][1] = *(const uint32_t*)&AL[aoff + 8 * ASTRIDE];
                al[mt][2] = *(const uint32_t*)&AL[aoff + 8];
                al[mt][3] = *(const uint32_t*)&AL[aoff + 8 * ASTRIDE + 8];
            }
#pragma unroll
            for (int nt = 0; nt < 4; nt++) {
                int boff = (wn * 32 + nt * 8 + qr) * ASTRIDE + qc * 2 + ks * 16;
                bh[nt][0] = *(const uint32_t*)&BH[boff];
                bh[nt][1] = *(const uint32_t*)&BH[boff + 8];
                bl[nt][0] = *(const uint32_t*)&BL[boff];
                bl[nt][1] = *(const uint32_t*)&BL[boff + 8];
            }
#pragma unroll
            for (int mt = 0; mt < 2; mt++)
#pragma unroll
                for (int nt = 0; nt < 4; nt++) {
                    bmma(acc[mt][nt], ah[mt], bh[nt]);
                    bmma(acc[mt][nt], ah[mt], bl[nt]);
                    bmma(acc[mt][nt], al[mt], bh[nt]);
                }
        }
        __syncthreads();
    }

    // ---------- phase 2 setup: S^T into smem + A graphs ----------
#pragma unroll
    for (int mt = 0; mt < 2; mt++)
#pragma unroll
        for (int nt = 0; nt < 4; nt++) {
            int src0 = wm * 32 + mt * 16 + qr;
            int f0 = wn * 32 + nt * 8 + qc * 2;
            __nv_bfloat16 h, l;
            split_bf16(acc[mt][nt][0], h, l); SH[f0 * SSTRIDE + src0] = h; SL[f0 * SSTRIDE + src0] = l;
            split_bf16(acc[mt][nt][1], h, l); SH[(f0 + 1) * SSTRIDE + src0] = h; SL[(f0 + 1) * SSTRIDE + src0] = l;
            split_bf16(acc[mt][nt][2], h, l); SH[f0 * SSTRIDE + src0 + 8] = h; SL[f0 * SSTRIDE + src0 + 8] = l;
            split_bf16(acc[mt][nt][3], h, l); SH[(f0 + 1) * SSTRIDE + src0 + 8] = h; SL[(f0 + 1) * SSTRIDE + src0 + 8] = l;
        }
#pragma unroll
    for (int u = 0; u < 16; u++) {
        int i = tid + u * 256;
        int g = i >> 10, rem = i & 1023;
        int dr = rem >> 5, sc = rem & 31;
        float v = (dr < NPG && sc < NPG) ? g_A[(size_t)(g0 + g) * 900 + dr * NPG + sc] : 0.f;
        __nv_bfloat16 h, l; split_bf16(v, h, l);
        GH[g * 1280 + dr * ASTRIDE + sc] = h;
        GL[g * 1280 + dr * ASTRIDE + sc] = l;
    }
    __syncthreads();

    // ---------- phase 2: out = A_g @ S ----------
#pragma unroll
    for (int mt = 0; mt < 2; mt++)
#pragma unroll
        for (int nt = 0; nt < 4; nt++)
#pragma unroll
            for (int i = 0; i < 4; i++) acc[mt][nt][i] = 0.f;

#pragma unroll
    for (int ks = 0; ks < 2; ks++) {
        uint32_t ah[2][4], al[2][4], bh[4][2], bl[4][2];
#pragma unroll
        for (int mt = 0; mt < 2; mt++) {
            int aoff = wm * 1280 + (mt * 16 + qr) * ASTRIDE + qc * 2 + ks * 16;
            ah[mt][0] = *(const uint32_t*)&GH[aoff];
            ah[mt][1] = *(const uint32_t*)&GH[aoff + 8 * ASTRIDE];
            ah[mt][2] = *(const uint32_t*)&GH[aoff + 8];
            ah[mt][3] = *(const uint32_t*)&GH[aoff + 8 * ASTRIDE + 8];
            al[mt][0] = *(const uint32_t*)&GL[aoff];
            al[mt][1] = *(const uint32_t*)&GL[aoff + 8 * ASTRIDE];
            al[mt][2] = *(const uint32_t*)&GL[aoff + 8];
            al[mt][3] = *(const uint32_t*)&GL[aoff + 8 * ASTRIDE + 8];
        }
#pragma unroll
        for (int nt = 0; nt < 4; nt++) {
            int boff = (wn * 32 + nt * 8 + qr) * SSTRIDE + wm * 32 + qc * 2 + ks * 16;
            bh[nt][0] = *(const uint32_t*)&SH[boff];
            bh[nt][1] = *(const uint32_t*)&SH[boff + 8];
            bl[nt][0] = *(const uint32_t*)&SL[boff];
            bl[nt][1] = *(const uint32_t*)&SL[boff + 8];
        }
#pragma unroll
        for (int mt = 0; mt < 2; mt++)
#pragma unroll
            for (int nt = 0; nt < 4; nt++) {
                bmma(acc[mt][nt], ah[mt], bh[nt]);
                bmma(acc[mt][nt], ah[mt], bl[nt]);
                bmma(acc[mt][nt], al[mt], bh[nt]);
            }
    }

    // ---------- epilogue ----------
    int g = g0 + wm;
    float pp[4][2];
#pragma unroll
    for (int nt = 0; nt < 4; nt++) { pp[nt][0] = 0.f; pp[nt][1] = 0.f; }

#pragma unroll
    for (int mt = 0; mt < 2; mt++)
#pragma unroll
        for (int nt = 0; nt < 4; nt++) {
            int dst0 = mt * 16 + qr;
            int dst1 = dst0 + 8;
            int f = colBase + wn * 32 + nt * 8 + qc * 2;
            float bb0 = bias[f], bb1 = bias[f + 1];
            float v0 = fmaxf(acc[mt][nt][0] + bb0, 0.f);
            float v1 = fmaxf(acc[mt][nt][1] + bb1, 0.f);
            float v2 = fmaxf(acc[mt][nt][2] + bb0, 0.f);
            float v3 = fmaxf(acc[mt][nt][3] + bb1, 0.f);
            if (POOL) {
                pp[nt][0] += v0; pp[nt][1] += v1;
                if (dst1 < NPG) { pp[nt][0] += v2; pp[nt][1] += v3; }
            } else {
                __nv_bfloat16 h0, l0, h1, l1;
                split_bf16(v0, h0, l0); split_bf16(v1, h1, l1);
                __nv_bfloat162 H, L;
                H.x = h0; H.y = h1; L.x = l0; L.y = l1;
                size_t o0 = ((size_t)g * 32 + dst0) * N + f;
                *(__nv_bfloat162*)&Oh[o0] = H;
                *(__nv_bfloat162*)&Ol[o0] = L;
                split_bf16(v2, h0, l0); split_bf16(v3, h1, l1);
                H.x = h0; H.y = h1; L.x = l0; L.y = l1;
                size_t o1 = ((size_t)g * 32 + dst1) * N + f;
                *(__nv_bfloat162*)&Oh[o1] = H;
                *(__nv_bfloat162*)&Ol[o1] = L;
            }
        }
    if (POOL) {
#pragma unroll
        for (int nt = 0; nt < 4; nt++) {
#pragma unroll
            for (int o = 4; o < 32; o <<= 1) {
                pp[nt][0] += __shfl_xor_sync(0xffffffffu, pp[nt][0], o);
                pp[nt][1] += __shfl_xor_sync(0xffffffffu, pp[nt][1], o);
            }
            if (qr == 0) {
                int f = colBase + wn * 32 + nt * 8 + qc * 2;
                pool[(size_t)g * N + f]     = pp[nt][0] * (1.0f / NPG);
                pool[(size_t)g * N + f + 1] = pp[nt][1] * (1.0f / NPG);
            }
        }
    }
}

// ============ plane-based mma GEMM (cell_fc1): C=act(A@B+bias) f32 out ============
template<bool BIAS, bool RELU>
__global__ void __launch_bounds__(256) mma_gemm(const __nv_bfloat16* __restrict__ Ah,
                                                const __nv_bfloat16* __restrict__ Al,
                                                const __nv_bfloat16* __restrict__ Wth,
                                                const __nv_bfloat16* __restrict__ Wtl,
                                                const float* __restrict__ bias,
                                                float* __restrict__ C,
                                                int M, int N, int K) {
    __shared__ __nv_bfloat16 AH[128 * ASTRIDE];
    __shared__ __nv_bfloat16 AL[128 * ASTRIDE];
    __shared__ __nv_bfloat16 BH[64 * ASTRIDE];
    __shared__ __nv_bfloat16 BL[64 * ASTRIDE];
    int tid = threadIdx.x;
    int wid = tid >> 5, lane = tid & 31;
    int wm = wid >> 1, wn = wid & 1;
    int qr = lane >> 2, qc = lane & 3;
    int rowBase = blockIdx.x * 128;
    int colBase = blockIdx.y * 64;

    float acc[2][4][4];
#pragma unroll
    for (int mt = 0; mt < 2; mt++)
#pragma unroll
        for (int nt = 0; nt < 4; nt++)
#pragma unroll
            for (int i = 0; i < 4; i++) acc[mt][nt][i] = 0.f;

    int KC = (K + 31) / 32;
    for (int c = 0; c < KC; c++) {
        int k0 = c * 32;
#pragma unroll
        for (int u = 0; u < 8; u++) {
            int slot = tid + u * 256;
            int r = slot >> 4, p = slot & 15;
            int k = k0 + p * 2;
            uint32_t uh = 0, ul = 0;
            if (k < K) {
                size_t off = (size_t)(rowBase + r) * K + k;
                uh = *(const uint32_t*)&Ah[off];
                ul = *(const uint32_t*)&Al[off];
            }
            *(uint32_t*)&AH[r * ASTRIDE + p * 2] = uh;
            *(uint32_t*)&AL[r * ASTRIDE + p * 2] = ul;
        }
#pragma unroll
        for (int u = 0; u < 4; u++) {
            int slot = tid + u * 256;
            int n = slot >> 4, p = slot & 15;
            int k = k0 + p * 2;
            uint32_t uh = 0, ul = 0;
            if (k < K) {
                size_t off = (size_t)(colBase + n) * K + k;
                uh = *(const uint32_t*)&Wth[off];
                ul = *(const uint32_t*)&Wtl[off];
            }
            *(uint32_t*)&BH[n * ASTRIDE + p * 2] = uh;
            *(uint32_t*)&BL[n * ASTRIDE + p * 2] = ul;
        }
        __syncthreads();
#pragma unroll
        for (int ks = 0; ks < 2; ks++) {
            uint32_t ah[2][4], al[2][4], bh[4][2], bl[4][2];
#pragma unroll
            for (int mt = 0; mt < 2; mt++) {
                int aoff = (wm * 32 + mt * 16 + qr) * ASTRIDE + qc * 2 + ks * 16;
                ah[mt][0] = *(const uint32_t*)&AH[aoff];
                ah[mt][1] = *(const uint32_t*)&AH[aoff + 8 * ASTRIDE];
                ah[mt][2] = *(const uint32_t*)&AH[aoff + 8];
                ah[mt][3] = *(const uint32_t*)&AH[aoff + 8 * ASTRIDE + 8];
                al[mt][0] = *(const uint32_t*)&AL[aoff];
                al[mt][1] = *(const uint32_t*)&AL[aoff + 8 * ASTRIDE];
                al[mt][2] = *(const uint32_t*)&AL[aoff + 8];
                al[mt][3] = *(const uint32_t*)&AL[aoff + 8 * ASTRIDE + 8];
            }
#pragma unroll
            for (int nt = 0; nt < 4; nt++) {
                int boff = (wn * 32 + nt * 8 + qr) * ASTRIDE + qc * 2 + ks * 16;
                bh[nt][0] = *(const uint32_t*)&BH[boff];
                bh[nt][1] = *(const uint32_t*)&BH[boff + 8];
                bl[nt][0] = *(const uint32_t*)&BL[boff];
                bl[nt][1] = *(const uint32_t*)&BL[boff + 8];
            }
#pragma unroll
            for (int mt = 0; mt < 2; mt++)
#pragma unroll
                for (int nt = 0; nt < 4; nt++) {
                    bmma(acc[mt][nt], ah[mt], bh[nt]);
                    bmma(acc[mt][nt], ah[mt], bl[nt]);
                    bmma(acc[mt][nt], al[mt], bh[nt]);
                }
        }
        __syncthreads();
    }
#pragma unroll
    for (int mt = 0; mt < 2; mt++)
#pragma unroll
        for (int nt = 0; nt < 4; nt++) {
            int row = rowBase + wm * 32 + mt * 16 + qr;
            int col = colBase + wn * 32 + nt * 8 + qc * 2;
            float v0 = acc[mt][nt][0], v1 = acc[mt][nt][1];
            float v2 = acc[mt][nt][2], v3 = acc[mt][nt][3];
            if (BIAS) {
                float bb0 = bias[col], bb1 = bias[col + 1];
                v0 += bb0; v1 += bb1; v2 += bb0; v3 += bb1;
            }
            if (RELU) {
                v0 = fmaxf(v0, 0.f); v1 = fmaxf(v1, 0.f);
                v2 = fmaxf(v2, 0.f); v3 = fmaxf(v3, 0.f);
            }
            *(float2*)&C[(size_t)row * N + col] = make_float2(v0, v1);
            *(float2*)&C[(size_t)(row + 8) * N + col] = make_float2(v2, v3);
        }
}

// ---------------- fp32 tiled GEMM (small layers) ----------------
template<bool BIAS, bool RELU>
__global__ void gemm_kernel(const float* __restrict__ A, const float* __restrict__ B,
                            const float* __restrict__ bias, float* __restrict__ C,
                            int M, int N, int K) {
    __shared__ float As[16][64];
    __shared__ float Bs[16][64];
    int tid = threadIdx.x;
    int tx = tid & 15, ty = tid >> 4;
    int rowBase = blockIdx.x * 64;
    int colBase = blockIdx.y * 64;
    float acc[4][4] = {};
    for (int k0 = 0; k0 < K; k0 += 16) {
#pragma unroll
        for (int u = 0; u < 4; u++) {
            int flat = tid + u * 256;
            int m = flat >> 4, kk = flat & 15;
            int gr = rowBase + m, gk = k0 + kk;
            As[kk][m] = (gr < M && gk < K) ? A[(size_t)gr * K + gk] : 0.f;
        }
#pragma unroll
        for (int u = 0; u < 4; u++) {
            int flat = tid + u * 256;
            int kk = flat >> 6, n = flat & 63;
            int gk = k0 + kk, gc = colBase + n;
            Bs[kk][n] = (gk < K && gc < N) ? B[(size_t)gk * N + gc] : 0.f;
        }
        __syncthreads();
#pragma unroll
        for (int kk = 0; kk < 16; kk++) {
            float a[4], b[4];
#pragma unroll
            for (int i = 0; i < 4; i++) a[i] = As[kk][ty * 4 + i];
#pragma unroll
            for (int j = 0; j < 4; j++) b[j] = Bs[kk][tx * 4 + j];
#pragma unroll
            for (int i = 0; i < 4; i++)
#pragma unroll
                for (int j = 0; j < 4; j++) acc[i][j] += a[i] * b[j];
        }
        __syncthreads();
    }
#pragma unroll
    for (int i = 0; i < 4; i++) {
        int r = rowBase + ty * 4 + i;
        if (r >= M) continue;
#pragma unroll
        for (int j = 0; j < 4; j++) {
            int c = colBase + tx * 4 + j;
            if (c >= N) continue;
            float v = acc[i][j];
            if (BIAS) v += bias[c];
            if (RELU) v = fmaxf(v, 0.f);
            C[(size_t)r * N + c] = v;
        }
    }
}

// ---------------- combiner head: one warp per graph ----------------
__global__ void combiner_kernel(const float* __restrict__ drug, const float* __restrict__ cell,
                                const float* __restrict__ Wm1, const float* __restrict__ bm1,
                                const float* __restrict__ Wm2, const float* __restrict__ bm2,
                                const float* __restrict__ Wo, const float* __restrict__ bo,
                                float* __restrict__ out) {
    int gwarp = (blockIdx.x * blockDim.x + threadIdx.x) >> 5;
    int lane = threadIdx.x & 31;
    int w = threadIdx.x >> 5;
    if (gwarp >= N_GRAPHS) return;
    __shared__ float s_comb[8][128];
    __shared__ float s_z1[8][64];
    __shared__ float s_z2[8][32];
    for (int u = lane; u < 64; u += 32) {
        s_comb[w][u] = drug[(size_t)gwarp * 64 + u];
        s_comb[w][64 + u] = cell[(size_t)gwarp * 64 + u];
    }
    __syncwarp();
    for (int j = lane; j < 64; j += 32) {
        float acc = bm1[j];
        for (int k = 0; k < 128; k++) acc += s_comb[w][k] * Wm1[k * 64 + j];
        s_z1[w][j] = fmaxf(acc, 0.f);
    }
    __syncwarp();
    {
        float acc = bm2[lane];
        for (int k = 0; k < 64; k++) acc += s_z1[w][k] * Wm2[k * 32 + lane];
        s_z2[w][lane] = fmaxf(acc, 0.f);
    }
    __syncwarp();
    float v = s_z2[w][lane] * Wo[lane];
#pragma unroll
    for (int o = 16; o > 0; o >>= 1) v += __shfl_down_sync(0xffffffffu, v, o);
    if (lane == 0) out[gwarp] = v + bo[0];
}

// ---------------- launch ----------------
extern "C" void kernel_launch(void* const* d_in, const int* in_sizes, int n_in,
                              void* d_out, int out_size) {
    const float* x     = (const float*)d_in[0];
    const int*   ei    = (const int*)d_in[1];
    const float* cellf = (const float*)d_in[3];
    const float* W1  = (const float*)d_in[4];
    const float* b1  = (const float*)d_in[5];
    const float* W2  = (const float*)d_in[6];
    const float* b2  = (const float*)d_in[7];
    const float* W3  = (const float*)d_in[8];
    const float* b3  = (const float*)d_in[9];
    const float* Wd  = (const float*)d_in[10];
    const float* bd  = (const float*)d_in[11];
    const float* Wc1 = (const float*)d_in[12];
    const float* bc1 = (const float*)d_in[13];
    const float* Wc2 = (const float*)d_in[14];
    const float* bc2 = (const float*)d_in[15];
    const float* Wm1 = (const float*)d_in[16];
    const float* bm1 = (const float*)d_in[17];
    const float* Wm2 = (const float*)d_in[18];
    const float* bm2 = (const float*)d_in[19];
    const float* Wo  = (const float*)d_in[20];
    const float* bo  = (const float*)d_in[21];
    float* out = (float*)d_out;

    __nv_bfloat16 *dxh, *dxl, *dwh, *dwl, *dch, *dcl, *dh1h, *dh1l, *dh2h, *dh2l;
    float *dPool, *dDrug, *dC1, *dCell;
    cudaGetSymbolAddress((void**)&dxh,  g_xh);
    cudaGetSymbolAddress((void**)&dxl,  g_xl);
    cudaGetSymbolAddress((void**)&dwh,  g_wh);
    cudaGetSymbolAddress((void**)&dwl,  g_wl);
    cudaGetSymbolAddress((void**)&dch,  g_ch);
    cudaGetSymbolAddress((void**)&dcl,  g_cl);
    cudaGetSymbolAddress((void**)&dh1h, g_h1h);
    cudaGetSymbolAddress((void**)&dh1l, g_h1l);
    cudaGetSymbolAddress((void**)&dh2h, g_h2h);
    cudaGetSymbolAddress((void**)&dh2l, g_h2l);
    cudaGetSymbolAddress((void**)&dPool, g_pool);
    cudaGetSymbolAddress((void**)&dDrug, g_drug);
    cudaGetSymbolAddress((void**)&dC1,   g_cell1);
    cudaGetSymbolAddress((void**)&dCell, g_cell);

    const int GCN_SMEM = 55296;
    cudaFuncSetAttribute(gcn_layer<true,  false>, cudaFuncAttributeMaxDynamicSharedMemorySize, GCN_SMEM);
    cudaFuncSetAttribute(gcn_layer<false, false>, cudaFuncAttributeMaxDynamicSharedMemorySize, GCN_SMEM);
    cudaFuncSetAttribute(gcn_layer<false, true>,  cudaFuncAttributeMaxDynamicSharedMemorySize, GCN_SMEM);

    // 0) pre-split inputs and weights into bf16 hi/lo planes
    {
        int npx = N_NODES * F_NODE / 2;
        split_pairs_kernel<<<(npx + 255) / 256, 256>>>(
            (const float2*)x, (__nv_bfloat162*)dxh, (__nv_bfloat162*)dxl, npx);
        int npc = N_GRAPHS * 1000 / 2;
        split_pairs_kernel<<<(npc + 255) / 256, 256>>>(
            (const float2*)cellf, (__nv_bfloat162*)dch, (__nv_bfloat162*)dcl, npc);
        split_w_kernel<<<(WTOT + 255) / 256, 256>>>(W1, W2, W3, Wc1);
    }

    // 1) build normalized adjacency
    init_kernel<<<(N_GRAPHS * 900 + 255) / 256, 256>>>();
    deg_kernel<<<(N_EDGES + 255) / 256, 256>>>(ei);
    dinv_kernel<<<(N_NODES + 255) / 256, 256>>>();
    buildA_kernel<<<(N_EDGES + 255) / 256, 256>>>(ei);

    const int GB = N_GRAPHS / 4;  // 2048 blocks (4 graphs each)

    // 2) three fused GCN layers (padded-32 bf16 plane layout between layers)
    gcn_layer<true,  false><<<dim3(GB, 1), 256, GCN_SMEM>>>(dxh, dxl, dwh + WOFF1, dwl + WOFF1, b1, dh1h, dh1l, nullptr, F_NODE, 64);
    gcn_layer<false, false><<<dim3(GB, 2), 256, GCN_SMEM>>>(dh1h, dh1l, dwh + WOFF2, dwl + WOFF2, b2, dh2h, dh2l, nullptr, 64, 128);
    gcn_layer<false, true ><<<dim3(GB, 4), 256, GCN_SMEM>>>(dh2h, dh2l, dwh + WOFF3, dwl + WOFF3, b3, nullptr, nullptr, dPool, 128, 256);

    // 3) drug embed: drug = pool @ Wd + bd (fp32, tiny)
    gemm_kernel<true, false><<<dim3(N_GRAPHS / 64, 1), 256>>>(dPool, Wd, bd, dDrug, N_GRAPHS, 64, 256);

    // 4) cell branch: fc1 on tensor cores (K=1000), fc2 fp32
    mma_gemm<true, true><<<dim3(N_GRAPHS / 128, 2), 256>>>(dch, dcl, dwh + WOFFC, dwl + WOFFC, bc1, dC1, N_GRAPHS, 128, 1000);
    gemm_kernel<true, false><<<dim3(N_GRAPHS / 64, 1), 256>>>(dC1, Wc2, bc2, dCell, N_GRAPHS, 64, 128);

    // 5) combiner head
    combiner_kernel<<<N_GRAPHS / 8, 256>>>(dDrug, dCell, Wm1, bm1, Wm2, bm2, Wo, bo, out);
}

// round 15
// speedup vs baseline: 2.3723x; 1.3472x over previous
#include <cuda_runtime.h>
#include <cuda_bf16.h>
#include <cstdint>

#define N_NODES 245760
#define N_GRAPHS 8192
#define N_EDGES 1000000
#define NPG 30
#define F_NODE 78
#define HID 64

// weight plane offsets (transposed [n][k] layout)
#define WOFF1 0
#define WOFF2 4992        // 78*64
#define WOFF3 13184       // +64*128
#define WOFFC 45952       // +128*256
#define WTOT  173952      // +1000*128

// ---------------- scratch (static device globals; no allocation) ----------------
__device__ float g_deg[N_NODES];
__device__ float g_dinv[N_NODES];
__device__ float g_A[(size_t)N_GRAPHS * 900];            // 29.5 MB  A[g][dst][src]
__device__ __nv_bfloat16 g_wh[WTOT];
__device__ __nv_bfloat16 g_wl[WTOT];
__device__ __nv_bfloat16 g_ch[(size_t)N_GRAPHS * 1000];
__device__ __nv_bfloat16 g_cl[(size_t)N_GRAPHS * 1000];
__device__ float g_pool[(size_t)N_GRAPHS * 256];
__device__ float g_drug[(size_t)N_GRAPHS * 64];
__device__ float g_cell1[(size_t)N_GRAPHS * 128];
__device__ float g_cell[(size_t)N_GRAPHS * 64];

__device__ __forceinline__ void split_bf16(float v, __nv_bfloat16& h, __nv_bfloat16& l) {
    h = __float2bfloat16(v);
    l = __float2bfloat16(v - __bfloat162float(h));
}

// ---------------- setup: pre-split cell features / weights ----------------
__global__ void split_pairs_kernel(const float2* __restrict__ in,
                                   __nv_bfloat162* __restrict__ oh,
                                   __nv_bfloat162* __restrict__ ol, int npairs) {
    int i = blockIdx.x * blockDim.x + threadIdx.x;
    if (i >= npairs) return;
    float2 v = in[i];
    __nv_bfloat16 h0, l0, h1, l1;
    split_bf16(v.x, h0, l0);
    split_bf16(v.y, h1, l1);
    __nv_bfloat162 H; H.x = h0; H.y = h1;
    __nv_bfloat162 L; L.x = l0; L.y = l1;
    oh[i] = H; ol[i] = L;
}

__global__ void split_w_kernel(const float* __restrict__ W1, const float* __restrict__ W2,
                               const float* __restrict__ W3, const float* __restrict__ Wc1) {
    int i = blockIdx.x * blockDim.x + threadIdx.x;
    const float* src; int K, N, off, j;
    if (i < WOFF2)      { src = W1;  K = 78;   N = 64;  off = WOFF1; j = i; }
    else if (i < WOFF3) { src = W2;  K = 64;   N = 128; off = WOFF2; j = i - WOFF2; }
    else if (i < WOFFC) { src = W3;  K = 128;  N = 256; off = WOFF3; j = i - WOFF3; }
    else if (i < WTOT)  { src = Wc1; K = 1000; N = 128; off = WOFFC; j = i - WOFFC; }
    else return;
    int n = j / K, k = j % K;
    float v = src[(size_t)k * N + n];
    __nv_bfloat16 h, l; split_bf16(v, h, l);
    g_wh[off + j] = h;
    g_wl[off + j] = l;
}

// ---------------- edge / degree kernels ----------------
__global__ void init_kernel() {
    int i = blockIdx.x * blockDim.x + threadIdx.x;
    size_t total = (size_t)N_GRAPHS * 900;
    if (i < (int)total) g_A[i] = 0.f;
    if (i < N_NODES) g_deg[i] = 1.0f;   // self-loop
}
__global__ void deg_kernel(const int* __restrict__ ei) {
    int e = blockIdx.x * blockDim.x + threadIdx.x;
    if (e >= N_EDGES) return;
    atomicAdd(&g_deg[ei[N_EDGES + e]], 1.0f);
}
__global__ void dinv_kernel() {
    int i = blockIdx.x * blockDim.x + threadIdx.x;
    if (i >= N_NODES) return;
    float dinv = rsqrtf(g_deg[i]);
    g_dinv[i] = dinv;
    int g = i / NPG, l = i % NPG;
    g_A[(size_t)g * 900 + l * NPG + l] = dinv * dinv;
}
__global__ void buildA_kernel(const int* __restrict__ ei) {
    int e = blockIdx.x * blockDim.x + threadIdx.x;
    if (e >= N_EDGES) return;
    int s = ei[e], d = ei[N_EDGES + e];
    int g = d / NPG;
    int ls = s % NPG, ld = d % NPG;
    atomicAdd(&g_A[(size_t)g * 900 + ld * NPG + ls], g_dinv[s] * g_dinv[d]);
}

// ---------------- mma helpers ----------------
#define ASTRIDE 40    // GA smem stride
#define SSTRIDE 136   // S^T / W / H2 stride
#define H1STRIDE 72
#define XSTRIDE 104

__device__ __forceinline__ void bmma(float* d, const uint32_t* a, const uint32_t* b) {
    asm volatile(
        "mma.sync.aligned.m16n8k16.row.col.f32.bf16.bf16.f32 "
        "{%0,%1,%2,%3},{%4,%5,%6,%7},{%8,%9},{%0,%1,%2,%3};\n"
        : "+f"(d[0]), "+f"(d[1]), "+f"(d[2]), "+f"(d[3])
        : "r"(a[0]), "r"(a[1]), "r"(a[2]), "r"(a[3]), "r"(b[0]), "r"(b[1]));
}

// mega-kernel smem layout (bytes)
#define GH_OFF  0
#define GL_OFF  10240
#define H1H_OFF 20480
#define H1L_OFF 38912
#define H2H_OFF 57344
#define H2L_OFF 92160
#define STH_OFF 126976
#define STL_OFF 144384
#define WHS_OFF 161792
#define WLS_OFF 179200
#define MEGA_SMEM 196608
#define XH_OFF  H2H_OFF            // L1 x tile aliases H2 region
#define XL_OFF  (H2H_OFF + 26624)

__device__ __forceinline__ void zero_acc(float acc[2][4][4]) {
#pragma unroll
    for (int mt = 0; mt < 2; mt++)
#pragma unroll
        for (int nt = 0; nt < 4; nt++)
#pragma unroll
            for (int i = 0; i < 4; i++) acc[mt][nt][i] = 0.f;
}

// phase-1: acc += Hin(block rows) @ W(coltile), frags straight from smem planes
__device__ __forceinline__ void p1_mma(const __nv_bfloat16* HH, const __nv_bfloat16* HL, int hs, int KC,
                                       const __nv_bfloat16* WHs, const __nv_bfloat16* WLs,
                                       int wm, int wn, int qr, int qc, float acc[2][4][4]) {
    for (int kc = 0; kc < KC; kc++) {
#pragma unroll
        for (int ks = 0; ks < 2; ks++) {
            int kk = kc * 32 + ks * 16 + qc * 2;
            uint32_t ah[2][4], al[2][4], bh[4][2], bl[4][2];
#pragma unroll
            for (int mt = 0; mt < 2; mt++) {
                const __nv_bfloat16* p = HH + (wm * 32 + mt * 16 + qr) * hs + kk;
                const __nv_bfloat16* q = HL + (wm * 32 + mt * 16 + qr) * hs + kk;
                ah[mt][0] = *(const uint32_t*)p;       ah[mt][1] = *(const uint32_t*)(p + 8 * hs);
                ah[mt][2] = *(const uint32_t*)(p + 8); ah[mt][3] = *(const uint32_t*)(p + 8 * hs + 8);
                al[mt][0] = *(const uint32_t*)q;       al[mt][1] = *(const uint32_t*)(q + 8 * hs);
                al[mt][2] = *(const uint32_t*)(q + 8); al[mt][3] = *(const uint32_t*)(q + 8 * hs + 8);
            }
#pragma unroll
            for (int nt = 0; nt < 4; nt++) {
                const __nv_bfloat16* p = WHs + (wn * 32 + nt * 8 + qr) * SSTRIDE + kk;
                const __nv_bfloat16* q = WLs + (wn * 32 + nt * 8 + qr) * SSTRIDE + kk;
                bh[nt][0] = *(const uint32_t*)p; bh[nt][1] = *(const uint32_t*)(p + 8);
                bl[nt][0] = *(const uint32_t*)q; bl[nt][1] = *(const uint32_t*)(q + 8);
            }
#pragma unroll
            for (int mt = 0; mt < 2; mt++)
#pragma unroll
                for (int nt = 0; nt < 4; nt++) {
                    bmma(acc[mt][nt], ah[mt], bh[nt]);
                    bmma(acc[mt][nt], ah[mt], bl[nt]);
                    bmma(acc[mt][nt], al[mt], bh[nt]);
                }
        }
    }
}

// store S transposed into S^T planes
__device__ __forceinline__ void store_st(const float acc[2][4][4],
                                         __nv_bfloat16* SH, __nv_bfloat16* SL,
                                         int wm, int wn, int qr, int qc) {
#pragma unroll
    for (int mt = 0; mt < 2; mt++)
#pragma unroll
        for (int nt = 0; nt < 4; nt++) {
            int src0 = wm * 32 + mt * 16 + qr;
            int f0 = wn * 32 + nt * 8 + qc * 2;
            __nv_bfloat16 h, l;
            split_bf16(acc[mt][nt][0], h, l); SH[f0 * SSTRIDE + src0] = h; SL[f0 * SSTRIDE + src0] = l;
            split_bf16(acc[mt][nt][1], h, l); SH[(f0 + 1) * SSTRIDE + src0] = h; SL[(f0 + 1) * SSTRIDE + src0] = l;
            split_bf16(acc[mt][nt][2], h, l); SH[f0 * SSTRIDE + src0 + 8] = h; SL[f0 * SSTRIDE + src0 + 8] = l;
            split_bf16(acc[mt][nt][3], h, l); SH[(f0 + 1) * SSTRIDE + src0 + 8] = h; SL[(f0 + 1) * SSTRIDE + src0 + 8] = l;
        }
}

// phase-2: acc = A_g @ S  (warp wm owns graph g0+wm)
__device__ __forceinline__ void p2_mma(const __nv_bfloat16* GH, const __nv_bfloat16* GL,
                                       const __nv_bfloat16* SH, const __nv_bfloat16* SL,
                                       int wm, int wn, int qr, int qc, float acc[2][4][4]) {
#pragma unroll
    for (int ks = 0; ks < 2; ks++) {
        uint32_t ah[2][4], al[2][4], bh[4][2], bl[4][2];
#pragma unroll
        for (int mt = 0; mt < 2; mt++) {
            int aoff = wm * 1280 + (mt * 16 + qr) * ASTRIDE + qc * 2 + ks * 16;
            ah[mt][0] = *(const uint32_t*)&GH[aoff];
            ah[mt][1] = *(const uint32_t*)&GH[aoff + 8 * ASTRIDE];
            ah[mt][2] = *(const uint32_t*)&GH[aoff + 8];
            ah[mt][3] = *(const uint32_t*)&GH[aoff + 8 * ASTRIDE + 8];
            al[mt][0] = *(const uint32_t*)&GL[aoff];
            al[mt][1] = *(const uint32_t*)&GL[aoff + 8 * ASTRIDE];
            al[mt][2] = *(const uint32_t*)&GL[aoff + 8];
            al[mt][3] = *(const uint32_t*)&GL[aoff + 8 * ASTRIDE + 8];
        }
#pragma unroll
        for (int nt = 0; nt < 4; nt++) {
            int boff = (wn * 32 + nt * 8 + qr) * SSTRIDE + wm * 32 + qc * 2 + ks * 16;
            bh[nt][0] = *(const uint32_t*)&SH[boff];
            bh[nt][1] = *(const uint32_t*)&SH[boff + 8];
            bl[nt][0] = *(const uint32_t*)&SL[boff];
            bl[nt][1] = *(const uint32_t*)&SL[boff + 8];
        }
#pragma unroll
        for (int mt = 0; mt < 2; mt++)
#pragma unroll
            for (int nt = 0; nt < 4; nt++) {
                bmma(acc[mt][nt], ah[mt], bh[nt]);
                bmma(acc[mt][nt], ah[mt], bl[nt]);
                bmma(acc[mt][nt], al[mt], bh[nt]);
            }
    }
}

// load one 64-col weight tile (full K, zero-padded) into WHs/WLs (stride 136)
__device__ __forceinline__ void load_wtile(const __nv_bfloat16* wh, const __nv_bfloat16* wl,
                                           int K, int KPAD, int colBase,
                                           __nv_bfloat16* WHs, __nv_bfloat16* WLs, int tid) {
    int pairs = KPAD >> 1;
    for (int idx = tid; idx < 64 * pairs; idx += 256) {
        int n = idx / pairs, p = idx - n * pairs;
        int k = p * 2;
        uint32_t uh = 0, ul = 0;
        if (k < K) {
            size_t o = (size_t)(colBase + n) * K + k;
            uh = *(const uint32_t*)&wh[o];
            ul = *(const uint32_t*)&wl[o];
        }
        *(uint32_t*)&WHs[n * SSTRIDE + k] = uh;
        *(uint32_t*)&WLs[n * SSTRIDE + k] = ul;
    }
}

// ============ MEGA: all 3 GCN layers, activations resident in smem ============
__global__ void __launch_bounds__(256) gcn_mega(const float* __restrict__ x,
                                                const float* __restrict__ b1,
                                                const float* __restrict__ b2,
                                                const float* __restrict__ b3,
                                                float* __restrict__ pool) {
    extern __shared__ char sm[];
    __nv_bfloat16* GH  = (__nv_bfloat16*)(sm + GH_OFF);
    __nv_bfloat16* GL  = (__nv_bfloat16*)(sm + GL_OFF);
    __nv_bfloat16* H1H = (__nv_bfloat16*)(sm + H1H_OFF);
    __nv_bfloat16* H1L = (__nv_bfloat16*)(sm + H1L_OFF);
    __nv_bfloat16* H2H = (__nv_bfloat16*)(sm + H2H_OFF);
    __nv_bfloat16* H2L = (__nv_bfloat16*)(sm + H2L_OFF);
    __nv_bfloat16* STH = (__nv_bfloat16*)(sm + STH_OFF);
    __nv_bfloat16* STL = (__nv_bfloat16*)(sm + STL_OFF);
    __nv_bfloat16* WHs = (__nv_bfloat16*)(sm + WHS_OFF);
    __nv_bfloat16* WLs = (__nv_bfloat16*)(sm + WLS_OFF);
    __nv_bfloat16* XH  = (__nv_bfloat16*)(sm + XH_OFF);
    __nv_bfloat16* XL  = (__nv_bfloat16*)(sm + XL_OFF);

    int tid = threadIdx.x;
    int wid = tid >> 5, lane = tid & 31;
    int wm = wid >> 1, wn = wid & 1;
    int qr = lane >> 2, qc = lane & 3;
    int g0 = blockIdx.x * 4;

    // --- load 4 graphs' adjacency (split) ---
#pragma unroll
    for (int u = 0; u < 16; u++) {
        int i = tid + u * 256;
        int g = i >> 10, rem = i & 1023;
        int dr = rem >> 5, sc = rem & 31;
        float v = (dr < NPG && sc < NPG) ? g_A[(size_t)(g0 + g) * 900 + dr * NPG + sc] : 0.f;
        __nv_bfloat16 h, l; split_bf16(v, h, l);
        GH[g * 1280 + dr * ASTRIDE + sc] = h;
        GL[g * 1280 + dr * ASTRIDE + sc] = l;
    }

    // --- L1: x tile (inline split) + W1 tile ---
    for (int idx = tid; idx < 128 * 48; idx += 256) {
        int r = idx / 48, p = idx - r * 48;
        int k = p * 2;
        int gg = g0 + (r >> 5), lr = r & 31;
        __nv_bfloat16 h0, l0, h1, l1;
        if (lr < NPG && k < F_NODE) {
            float2 v = *(const float2*)&x[(size_t)(gg * NPG + lr) * F_NODE + k];
            split_bf16(v.x, h0, l0);
            split_bf16(v.y, h1, l1);
        } else {
            h0 = l0 = h1 = l1 = __float2bfloat16(0.f);
        }
        __nv_bfloat162 H, L;
        H.x = h0; H.y = h1; L.x = l0; L.y = l1;
        *(__nv_bfloat162*)&XH[r * XSTRIDE + k] = H;
        *(__nv_bfloat162*)&XL[r * XSTRIDE + k] = L;
    }
    load_wtile(g_wh + WOFF1, g_wl + WOFF1, F_NODE, 96, 0, WHs, WLs, tid);
    __syncthreads();

    float acc[2][4][4];
    zero_acc(acc);
    p1_mma(XH, XL, XSTRIDE, 3, WHs, WLs, wm, wn, qr, qc, acc);
    store_st(acc, STH, STL, wm, wn, qr, qc);
    __syncthreads();
    zero_acc(acc);
    p2_mma(GH, GL, STH, STL, wm, wn, qr, qc, acc);
    // epilogue -> H1 smem (stride 72)
#pragma unroll
    for (int mt = 0; mt < 2; mt++)
#pragma unroll
        for (int nt = 0; nt < 4; nt++) {
            int dst0 = mt * 16 + qr, dst1 = dst0 + 8;
            int f = wn * 32 + nt * 8 + qc * 2;
            float bb0 = b1[f], bb1 = b1[f + 1];
            float v0 = fmaxf(acc[mt][nt][0] + bb0, 0.f);
            float v1 = fmaxf(acc[mt][nt][1] + bb1, 0.f);
            float v2 = fmaxf(acc[mt][nt][2] + bb0, 0.f);
            float v3 = fmaxf(acc[mt][nt][3] + bb1, 0.f);
            __nv_bfloat16 h0, l0, h1, l1;
            __nv_bfloat162 H, L;
            split_bf16(v0, h0, l0); split_bf16(v1, h1, l1);
            H.x = h0; H.y = h1; L.x = l0; L.y = l1;
            *(__nv_bfloat162*)&H1H[(wm * 32 + dst0) * H1STRIDE + f] = H;
            *(__nv_bfloat162*)&H1L[(wm * 32 + dst0) * H1STRIDE + f] = L;
            split_bf16(v2, h0, l0); split_bf16(v3, h1, l1);
            H.x = h0; H.y = h1; L.x = l0; L.y = l1;
            *(__nv_bfloat162*)&H1H[(wm * 32 + dst1) * H1STRIDE + f] = H;
            *(__nv_bfloat162*)&H1L[(wm * 32 + dst1) * H1STRIDE + f] = L;
        }

    // --- L2: 2 column chunks ---
    for (int cc = 0; cc < 2; cc++) {
        __syncthreads();
        load_wtile(g_wh + WOFF2, g_wl + WOFF2, 64, 64, cc * 64, WHs, WLs, tid);
        __syncthreads();
        zero_acc(acc);
        p1_mma(H1H, H1L, H1STRIDE, 2, WHs, WLs, wm, wn, qr, qc, acc);
        store_st(acc, STH, STL, wm, wn, qr, qc);
        __syncthreads();
        zero_acc(acc);
        p2_mma(GH, GL, STH, STL, wm, wn, qr, qc, acc);
#pragma unroll
        for (int mt = 0; mt < 2; mt++)
#pragma unroll
            for (int nt = 0; nt < 4; nt++) {
                int dst0 = mt * 16 + qr, dst1 = dst0 + 8;
                int f = cc * 64 + wn * 32 + nt * 8 + qc * 2;
                float bb0 = b2[f], bb1 = b2[f + 1];
                float v0 = fmaxf(acc[mt][nt][0] + bb0, 0.f);
                float v1 = fmaxf(acc[mt][nt][1] + bb1, 0.f);
                float v2 = fmaxf(acc[mt][nt][2] + bb0, 0.f);
                float v3 = fmaxf(acc[mt][nt][3] + bb1, 0.f);
                __nv_bfloat16 h0, l0, h1, l1;
                __nv_bfloat162 H, L;
                split_bf16(v0, h0, l0); split_bf16(v1, h1, l1);
                H.x = h0; H.y = h1; L.x = l0; L.y = l1;
                *(__nv_bfloat162*)&H2H[(wm * 32 + dst0) * SSTRIDE + f] = H;
                *(__nv_bfloat162*)&H2L[(wm * 32 + dst0) * SSTRIDE + f] = L;
                split_bf16(v2, h0, l0); split_bf16(v3, h1, l1);
                H.x = h0; H.y = h1; L.x = l0; L.y = l1;
                *(__nv_bfloat162*)&H2H[(wm * 32 + dst1) * SSTRIDE + f] = H;
                *(__nv_bfloat162*)&H2L[(wm * 32 + dst1) * SSTRIDE + f] = L;
            }
    }

    // --- L3: 4 column chunks, fused mean pool ---
    int g = g0 + wm;
    for (int cc = 0; cc < 4; cc++) {
        __syncthreads();
        load_wtile(g_wh + WOFF3, g_wl + WOFF3, 128, 128, cc * 64, WHs, WLs, tid);
        __syncthreads();
        zero_acc(acc);
        p1_mma(H2H, H2L, SSTRIDE, 4, WHs, WLs, wm, wn, qr, qc, acc);
        store_st(acc, STH, STL, wm, wn, qr, qc);
        __syncthreads();
        zero_acc(acc);
        p2_mma(GH, GL, STH, STL, wm, wn, qr, qc, acc);

        float pp[4][2];
#pragma unroll
        for (int nt = 0; nt < 4; nt++) { pp[nt][0] = 0.f; pp[nt][1] = 0.f; }
#pragma unroll
        for (int mt = 0; mt < 2; mt++)
#pragma unroll
            for (int nt = 0; nt < 4; nt++) {
                int dst1 = mt * 16 + qr + 8;
                int f = cc * 64 + wn * 32 + nt * 8 + qc * 2;
                float bb0 = b3[f], bb1 = b3[f + 1];
                float v0 = fmaxf(acc[mt][nt][0] + bb0, 0.f);
                float v1 = fmaxf(acc[mt][nt][1] + bb1, 0.f);
                float v2 = fmaxf(acc[mt][nt][2] + bb0, 0.f);
                float v3 = fmaxf(acc[mt][nt][3] + bb1, 0.f);
                pp[nt][0] += v0; pp[nt][1] += v1;
                if (dst1 < NPG) { pp[nt][0] += v2; pp[nt][1] += v3; }
            }
#pragma unroll
        for (int nt = 0; nt < 4; nt++) {
#pragma unroll
            for (int o = 4; o < 32; o <<= 1) {
                pp[nt][0] += __shfl_xor_sync(0xffffffffu, pp[nt][0], o);
                pp[nt][1] += __shfl_xor_sync(0xffffffffu, pp[nt][1], o);
            }
            if (qr == 0) {
                int f = cc * 64 + wn * 32 + nt * 8 + qc * 2;
                pool[(size_t)g * 256 + f]     = pp[nt][0] * (1.0f / NPG);
                pool[(size_t)g * 256 + f + 1] = pp[nt][1] * (1.0f / NPG);
            }
        }
    }
}

// ============ plane-based mma GEMM (cell_fc1) ============
template<bool BIAS, bool RELU>
__global__ void __launch_bounds__(256) mma_gemm(const __nv_bfloat16* __restrict__ Ah,
                                                const __nv_bfloat16* __restrict__ Al,
                                                const __nv_bfloat16* __restrict__ Wth,
                                                const __nv_bfloat16* __restrict__ Wtl,
                                                const float* __restrict__ bias,
                                                float* __restrict__ C,
                                                int M, int N, int K) {
    __shared__ __nv_bfloat16 AH[128 * ASTRIDE];
    __shared__ __nv_bfloat16 AL[128 * ASTRIDE];
    __shared__ __nv_bfloat16 BH[64 * ASTRIDE];
    __shared__ __nv_bfloat16 BL[64 * ASTRIDE];
    int tid = threadIdx.x;
    int wid = tid >> 5, lane = tid & 31;
    int wm = wid >> 1, wn = wid & 1;
    int qr = lane >> 2, qc = lane & 3;
    int rowBase = blockIdx.x * 128;
    int colBase = blockIdx.y * 64;

    float acc[2][4][4];
    zero_acc(acc);

    int KC = (K + 31) / 32;
    for (int c = 0; c < KC; c++) {
        int k0 = c * 32;
#pragma unroll
        for (int u = 0; u < 8; u++) {
            int slot = tid + u * 256;
            int r = slot >> 4, p = slot & 15;
            int k = k0 + p * 2;
            uint32_t uh = 0, ul = 0;
            if (k < K) {
                size_t off = (size_t)(rowBase + r) * K + k;
                uh = *(const uint32_t*)&Ah[off];
                ul = *(const uint32_t*)&Al[off];
            }
            *(uint32_t*)&AH[r * ASTRIDE + p * 2] = uh;
            *(uint32_t*)&AL[r * ASTRIDE + p * 2] = ul;
        }
#pragma unroll
        for (int u = 0; u < 4; u++) {
            int slot = tid + u * 256;
            int n = slot >> 4, p = slot & 15;
            int k = k0 + p * 2;
            uint32_t uh = 0, ul = 0;
            if (k < K) {
                size_t off = (size_t)(colBase + n) * K + k;
                uh = *(const uint32_t*)&Wth[off];
                ul = *(const uint32_t*)&Wtl[off];
            }
            *(uint32_t*)&BH[n * ASTRIDE + p * 2] = uh;
            *(uint32_t*)&BL[n * ASTRIDE + p * 2] = ul;
        }
        __syncthreads();
#pragma unroll
        for (int ks = 0; ks < 2; ks++) {
            uint32_t ah[2][4], al[2][4], bh[4][2], bl[4][2];
#pragma unroll
            for (int mt = 0; mt < 2; mt++) {
                int aoff = (wm * 32 + mt * 16 + qr) * ASTRIDE + qc * 2 + ks * 16;
                ah[mt][0] = *(const uint32_t*)&AH[aoff];
                ah[mt][1] = *(const uint32_t*)&AH[aoff + 8 * ASTRIDE];
                ah[mt][2] = *(const uint32_t*)&AH[aoff + 8];
                ah[mt][3] = *(const uint32_t*)&AH[aoff + 8 * ASTRIDE + 8];
                al[mt][0] = *(const uint32_t*)&AL[aoff];
                al[mt][1] = *(const uint32_t*)&AL[aoff + 8 * ASTRIDE];
                al[mt][2] = *(const uint32_t*)&AL[aoff + 8];
                al[mt][3] = *(const uint32_t*)&AL[aoff + 8 * ASTRIDE + 8];
            }
#pragma unroll
            for (int nt = 0; nt < 4; nt++) {
                int boff = (wn * 32 + nt * 8 + qr) * ASTRIDE + qc * 2 + ks * 16;
                bh[nt][0] = *(const uint32_t*)&BH[boff];
                bh[nt][1] = *(const uint32_t*)&BH[boff + 8];
                bl[nt][0] = *(const uint32_t*)&BL[boff];
                bl[nt][1] = *(const uint32_t*)&BL[boff + 8];
            }
#pragma unroll
            for (int mt = 0; mt < 2; mt++)
#pragma unroll
                for (int nt = 0; nt < 4; nt++) {
                    bmma(acc[mt][nt], ah[mt], bh[nt]);
                    bmma(acc[mt][nt], ah[mt], bl[nt]);
                    bmma(acc[mt][nt], al[mt], bh[nt]);
                }
        }
        __syncthreads();
    }
#pragma unroll
    for (int mt = 0; mt < 2; mt++)
#pragma unroll
        for (int nt = 0; nt < 4; nt++) {
            int row = rowBase + wm * 32 + mt * 16 + qr;
            int col = colBase + wn * 32 + nt * 8 + qc * 2;
            float v0 = acc[mt][nt][0], v1 = acc[mt][nt][1];
            float v2 = acc[mt][nt][2], v3 = acc[mt][nt][3];
            if (BIAS) {
                float bb0 = bias[col], bb1 = bias[col + 1];
                v0 += bb0; v1 += bb1; v2 += bb0; v3 += bb1;
            }
            if (RELU) {
                v0 = fmaxf(v0, 0.f); v1 = fmaxf(v1, 0.f);
                v2 = fmaxf(v2, 0.f); v3 = fmaxf(v3, 0.f);
            }
            *(float2*)&C[(size_t)row * N + col] = make_float2(v0, v1);
            *(float2*)&C[(size_t)(row + 8) * N + col] = make_float2(v2, v3);
        }
}

// ---------------- fp32 tiled GEMM (small layers) ----------------
template<bool BIAS, bool RELU>
__global__ void gemm_kernel(const float* __restrict__ A, const float* __restrict__ B,
                            const float* __restrict__ bias, float* __restrict__ C,
                            int M, int N, int K) {
    __shared__ float As[16][64];
    __shared__ float Bs[16][64];
    int tid = threadIdx.x;
    int tx = tid & 15, ty = tid >> 4;
    int rowBase = blockIdx.x * 64;
    int colBase = blockIdx.y * 64;
    float acc[4][4] = {};
    for (int k0 = 0; k0 < K; k0 += 16) {
#pragma unroll
        for (int u = 0; u < 4; u++) {
            int flat = tid + u * 256;
            int m = flat >> 4, kk = flat & 15;
            int gr = rowBase + m, gk = k0 + kk;
            As[kk][m] = (gr < M && gk < K) ? A[(size_t)gr * K + gk] : 0.f;
        }
#pragma unroll
        for (int u = 0; u < 4; u++) {
            int flat = tid + u * 256;
            int kk = flat >> 6, n = flat & 63;
            int gk = k0 + kk, gc = colBase + n;
            Bs[kk][n] = (gk < K && gc < N) ? B[(size_t)gk * N + gc] : 0.f;
        }
        __syncthreads();
#pragma unroll
        for (int kk = 0; kk < 16; kk++) {
            float a[4], b[4];
#pragma unroll
            for (int i = 0; i < 4; i++) a[i] = As[kk][ty * 4 + i];
#pragma unroll
            for (int j = 0; j < 4; j++) b[j] = Bs[kk][tx * 4 + j];
#pragma unroll
            for (int i = 0; i < 4; i++)
#pragma unroll
                for (int j = 0; j < 4; j++) acc[i][j] += a[i] * b[j];
        }
        __syncthreads();
    }
#pragma unroll
    for (int i = 0; i < 4; i++) {
        int r = rowBase + ty * 4 + i;
        if (r >= M) continue;
#pragma unroll
        for (int j = 0; j < 4; j++) {
            int c = colBase + tx * 4 + j;
            if (c >= N) continue;
            float v = acc[i][j];
            if (BIAS) v += bias[c];
            if (RELU) v = fmaxf(v, 0.f);
            C[(size_t)r * N + c] = v;
        }
    }
}

// ---------------- combiner head: one warp per graph ----------------
__global__ void combiner_kernel(const float* __restrict__ drug, const float* __restrict__ cell,
                                const float* __restrict__ Wm1, const float* __restrict__ bm1,
                                const float* __restrict__ Wm2, const float* __restrict__ bm2,
                                const float* __restrict__ Wo, const float* __restrict__ bo,
                                float* __restrict__ out) {
    int gwarp = (blockIdx.x * blockDim.x + threadIdx.x) >> 5;
    int lane = threadIdx.x & 31;
    int w = threadIdx.x >> 5;
    if (gwarp >= N_GRAPHS) return;
    __shared__ float s_comb[8][128];
    __shared__ float s_z1[8][64];
    __shared__ float s_z2[8][32];
    for (int u = lane; u < 64; u += 32) {
        s_comb[w][u] = drug[(size_t)gwarp * 64 + u];
        s_comb[w][64 + u] = cell[(size_t)gwarp * 64 + u];
    }
    __syncwarp();
    for (int j = lane; j < 64; j += 32) {
        float acc = bm1[j];
        for (int k = 0; k < 128; k++) acc += s_comb[w][k] * Wm1[k * 64 + j];
        s_z1[w][j] = fmaxf(acc, 0.f);
    }
    __syncwarp();
    {
        float acc = bm2[lane];
        for (int k = 0; k < 64; k++) acc += s_z1[w][k] * Wm2[k * 32 + lane];
        s_z2[w][lane] = fmaxf(acc, 0.f);
    }
    __syncwarp();
    float v = s_z2[w][lane] * Wo[lane];
#pragma unroll
    for (int o = 16; o > 0; o >>= 1) v += __shfl_down_sync(0xffffffffu, v, o);
    if (lane == 0) out[gwarp] = v + bo[0];
}

// ---------------- launch ----------------
extern "C" void kernel_launch(void* const* d_in, const int* in_sizes, int n_in,
                              void* d_out, int out_size) {
    const float* x     = (const float*)d_in[0];
    const int*   ei    = (const int*)d_in[1];
    const float* cellf = (const float*)d_in[3];
    const float* W1  = (const float*)d_in[4];
    const float* b1  = (const float*)d_in[5];
    const float* W2  = (const float*)d_in[6];
    const float* b2  = (const float*)d_in[7];
    const float* W3  = (const float*)d_in[8];
    const float* b3  = (const float*)d_in[9];
    const float* Wd  = (const float*)d_in[10];
    const float* bd  = (const float*)d_in[11];
    const float* Wc1 = (const float*)d_in[12];
    const float* bc1 = (const float*)d_in[13];
    const float* Wc2 = (const float*)d_in[14];
    const float* bc2 = (const float*)d_in[15];
    const float* Wm1 = (const float*)d_in[16];
    const float* bm1 = (const float*)d_in[17];
    const float* Wm2 = (const float*)d_in[18];
    const float* bm2 = (const float*)d_in[19];
    const float* Wo  = (const float*)d_in[20];
    const float* bo  = (const float*)d_in[21];
    float* out = (float*)d_out;

    __nv_bfloat16 *dwh, *dwl, *dch, *dcl;
    float *dPool, *dDrug, *dC1, *dCell;
    cudaGetSymbolAddress((void**)&dwh,  g_wh);
    cudaGetSymbolAddress((void**)&dwl,  g_wl);
    cudaGetSymbolAddress((void**)&dch,  g_ch);
    cudaGetSymbolAddress((void**)&dcl,  g_cl);
    cudaGetSymbolAddress((void**)&dPool, g_pool);
    cudaGetSymbolAddress((void**)&dDrug, g_drug);
    cudaGetSymbolAddress((void**)&dC1,   g_cell1);
    cudaGetSymbolAddress((void**)&dCell, g_cell);

    cudaFuncSetAttribute(gcn_mega, cudaFuncAttributeMaxDynamicSharedMemorySize, MEGA_SMEM);

    // 0) pre-split cell features and weights
    {
        int npc = N_GRAPHS * 1000 / 2;
        split_pairs_kernel<<<(npc + 255) / 256, 256>>>(
            (const float2*)cellf, (__nv_bfloat162*)dch, (__nv_bfloat162*)dcl, npc);
        split_w_kernel<<<(WTOT + 255) / 256, 256>>>(W1, W2, W3, Wc1);
    }

    // 1) build normalized adjacency
    init_kernel<<<(N_GRAPHS * 900 + 255) / 256, 256>>>();
    deg_kernel<<<(N_EDGES + 255) / 256, 256>>>(ei);
    dinv_kernel<<<(N_NODES + 255) / 256, 256>>>();
    buildA_kernel<<<(N_EDGES + 255) / 256, 256>>>(ei);

    // 2) fused 3-layer GCN + pool (activations never leave smem)
    gcn_mega<<<N_GRAPHS / 4, 256, MEGA_SMEM>>>(x, b1, b2, b3, dPool);

    // 3) drug embed: drug = pool @ Wd + bd (fp32, tiny)
    gemm_kernel<true, false><<<dim3(N_GRAPHS / 64, 1), 256>>>(dPool, Wd, bd, dDrug, N_GRAPHS, 64, 256);

    // 4) cell branch: fc1 on tensor cores (K=1000), fc2 fp32
    mma_gemm<true, true><<<dim3(N_GRAPHS / 128, 2), 256>>>(dch, dcl, dwh + WOFFC, dwl + WOFFC, bc1, dC1, N_GRAPHS, 128, 1000);
    gemm_kernel<true, false><<<dim3(N_GRAPHS / 64, 1), 256>>>(dC1, Wc2, bc2, dCell, N_GRAPHS, 64, 128);

    // 5) combiner head
    combiner_kernel<<<N_GRAPHS / 8, 256>>>(dDrug, dCell, Wm1, bm1, Wm2, bm2, Wo, bo, out);
}